// round 2
// baseline (speedup 1.0000x reference)
#include <cuda_runtime.h>
#include <math.h>

#define L_   1024
#define D_   512
#define H_   8
#define HD_  64
#define KF_  24
#define EPSF 1e-5f

// ---------------- static scratch (no allocs allowed) ----------------
__device__ float g_q[L_ * D_];
__device__ float g_k[L_ * D_];
__device__ float g_v[L_ * D_];
__device__ float g_ck[(size_t)KF_ * L_ * D_];   // conv(k_norm): [kf][l][c]
__device__ float g_cv[(size_t)KF_ * L_ * D_];   // conv(v_norm)
__device__ float g_gz[(size_t)H_ * L_ * HD_ * HD_]; // gated Z, then its cumsum (in place)
__device__ float g_sim[H_ * L_];
__device__ float g_gate[H_ * L_];
__device__ float g_coef[H_ * L_];
__device__ float g_ctxt[L_ * D_];

// ---------------- generic SGEMM: C[1024x512] = A[1024x512] @ B[512x512] + bias ----------------
__global__ void sgemm_bias_kernel(const float* __restrict__ A,
                                  const float* __restrict__ B,
                                  const float* __restrict__ bias,
                                  float* __restrict__ C) {
    __shared__ float As[64][17];
    __shared__ float Bs[16][64];
    const int tx = threadIdx.x, ty = threadIdx.y;
    const int tid = ty * 16 + tx;
    const int m0 = blockIdx.y * 64, n0 = blockIdx.x * 64;

    float acc[4][4] = {};
    for (int k0 = 0; k0 < 512; k0 += 16) {
        #pragma unroll
        for (int it = 0; it < 4; it++) {
            int e = tid + 256 * it;
            As[e >> 4][e & 15] = A[(m0 + (e >> 4)) * 512 + k0 + (e & 15)];
            Bs[e >> 6][e & 63] = B[(k0 + (e >> 6)) * 512 + n0 + (e & 63)];
        }
        __syncthreads();
        #pragma unroll
        for (int kk = 0; kk < 16; kk++) {
            float a[4], b[4];
            #pragma unroll
            for (int i = 0; i < 4; i++) a[i] = As[ty * 4 + i][kk];
            #pragma unroll
            for (int j = 0; j < 4; j++) b[j] = Bs[kk][tx * 4 + j];
            #pragma unroll
            for (int i = 0; i < 4; i++)
                #pragma unroll
                for (int j = 0; j < 4; j++)
                    acc[i][j] += a[i] * b[j];
        }
        __syncthreads();
    }
    #pragma unroll
    for (int i = 0; i < 4; i++)
        #pragma unroll
        for (int j = 0; j < 4; j++)
            C[(m0 + ty * 4 + i) * 512 + n0 + tx * 4 + j] = acc[i][j] + bias[n0 + tx * 4 + j];
}

// ---------------- sim + in-place L2 normalization of k,v ----------------
__global__ void norm_sim_kernel(const float* __restrict__ qk_scale) {
    const int l = blockIdx.x;
    const int c = threadIdx.x;          // 0..511
    const int head = c >> 6, d = c & 63;
    float q = g_q[l * 512 + c];
    float k = g_k[l * 512 + c];
    float v = g_v[l * 512 + c];

    __shared__ float sd[512], sk[512], sv[512];
    sd[c] = q * k; sk[c] = k * k; sv[c] = v * v;
    __syncthreads();
    for (int off = 32; off >= 1; off >>= 1) {
        if (d < off) {
            sd[c] += sd[c + off];
            sk[c] += sk[c + off];
            sv[c] += sv[c + off];
        }
        __syncthreads();
    }
    float nk = fmaxf(sqrtf(sk[head * 64]), 1e-12f);
    float nv = fmaxf(sqrtf(sv[head * 64]), 1e-12f);
    g_k[l * 512 + c] = k / nk;
    g_v[l * 512 + c] = v / nv;
    if (d == 0) g_sim[head * L_ + l] = sd[head * 64] * qk_scale[head];
}

// ---------------- causal conv as triangular Toeplitz GEMM tiles ----------------
// out[kf][l][c] = sum_{t<=l} f[l-t][kf] * u[t][c]
__global__ void conv_kernel(const float* __restrict__ filters) {
    const int z = blockIdx.z;
    const int kf = z % KF_;
    const bool isv = (z >= KF_);
    const float* __restrict__ u = isv ? g_v : g_k;
    float* __restrict__ o = (isv ? g_cv : g_ck) + (size_t)kf * (L_ * D_);

    const int l0 = blockIdx.y * 64, c0 = blockIdx.x * 64;
    const int tx = threadIdx.x, ty = threadIdx.y;
    const int tid = ty * 16 + tx;

    __shared__ float Us[64][64];
    __shared__ float fs[128];

    float acc[4][4] = {};
    for (int t0 = 0; t0 <= l0; t0 += 64) {
        #pragma unroll
        for (int it = 0; it < 16; it++) {
            int e = tid + 256 * it;
            Us[e >> 6][e & 63] = u[(t0 + (e >> 6)) * 512 + c0 + (e & 63)];
        }
        if (tid < 128) {
            int fi = l0 - t0 + tid - 63;
            fs[tid] = (fi >= 0 && fi < L_) ? filters[fi * KF_ + kf] : 0.0f;
        }
        __syncthreads();
        #pragma unroll 4
        for (int tt = 0; tt < 64; tt++) {
            float4 uv = *(const float4*)&Us[tt][tx * 4];
            float a[4];
            #pragma unroll
            for (int i = 0; i < 4; i++) a[i] = fs[ty * 4 + i - tt + 63];
            #pragma unroll
            for (int i = 0; i < 4; i++) {
                acc[i][0] += a[i] * uv.x;
                acc[i][1] += a[i] * uv.y;
                acc[i][2] += a[i] * uv.z;
                acc[i][3] += a[i] * uv.w;
            }
        }
        __syncthreads();
    }
    #pragma unroll
    for (int i = 0; i < 4; i++)
        #pragma unroll
        for (int j = 0; j < 4; j++)
            o[(l0 + ty * 4 + i) * 512 + c0 + tx * 4 + j] = acc[i][j];
}

// ---------------- Z = sum_kf v~ (x) k~, gate, write gated Z ----------------
__global__ void zgate_kernel(const float* __restrict__ Wg,
                             const float* __restrict__ bg,
                             const float* __restrict__ kvscale) {
    const int l = blockIdx.x, head = blockIdx.y;
    const int tid = threadIdx.x;   // 256

    __shared__ float kt[KF_ * 64];
    __shared__ float vt[KF_ * 64];
    for (int e = tid; e < KF_ * 64; e += 256) {
        int kf = e >> 6, d = e & 63;
        size_t base = (size_t)kf * (L_ * D_) + (size_t)l * 512 + head * 64 + d;
        kt[e] = g_ck[base];
        vt[e] = g_cv[base];
    }
    __syncthreads();

    float acc[16];
    float lp = 0.0f;
    #pragma unroll
    for (int r = 0; r < 16; r++) {
        int m = tid + 256 * r;          // m = d*64 + e
        int d = m >> 6, e = m & 63;
        float s = 0.0f;
        #pragma unroll
        for (int kf = 0; kf < KF_; kf++)
            s += vt[kf * 64 + d] * kt[kf * 64 + e];
        s *= kvscale[head * 4096 + m];
        acc[r] = s;
        lp += s * Wg[m];
    }

    __shared__ float red[256];
    red[tid] = lp;
    __syncthreads();
    for (int off = 128; off >= 1; off >>= 1) {
        if (tid < off) red[tid] += red[tid + off];
        __syncthreads();
    }
    float logit = red[0] + bg[0];
    float rl = fmaxf(logit, 0.0f);
    float gate = rl * rl + EPSF;
    if (tid == 0) g_gate[head * L_ + l] = gate;

    size_t ob = (size_t)head * (L_ * 4096) + (size_t)l * 4096;
    #pragma unroll
    for (int r = 0; r < 16; r++)
        g_gz[ob + tid + 256 * r] = gate * acc[r];
}

// ---------------- scalar online-softmax scan + gate cumsum -> per-l coefficient ----------------
__global__ void scan_kernel() {
    const int head = threadIdx.x;
    if (head >= H_) return;
    float m = -INFINITY, s = 0.0f, g = 0.0f;
    for (int l = 0; l < L_; l++) {
        float si = g_sim[head * L_ + l];
        float mn = fmaxf(m, si);
        s = s * expf(m - mn) + expf(si - mn);
        m = mn;
        g += g_gate[head * L_ + l];
        float w = expf(si - m) / (s + EPSF);
        float silu = w / (1.0f + expf(-w));
        g_coef[head * L_ + l] = (1.0f + silu) / (g + EPSF);
    }
}

// ---------------- in-place cumsum of gated Z over l ----------------
__global__ void cumsum_kernel() {
    const int head = blockIdx.y;
    const int c = blockIdx.x * 256 + threadIdx.x;   // 0..4095
    size_t base = (size_t)head * (L_ * 4096) + c;
    float acc = 0.0f;
    for (int l0 = 0; l0 < L_; l0 += 8) {
        float v[8];
        #pragma unroll
        for (int i = 0; i < 8; i++) v[i] = g_gz[base + (size_t)(l0 + i) * 4096];
        #pragma unroll
        for (int i = 0; i < 8; i++) { acc += v[i]; v[i] = acc; }
        #pragma unroll
        for (int i = 0; i < 8; i++) g_gz[base + (size_t)(l0 + i) * 4096] = v[i];
    }
}

// ---------------- ctxt[l, head*64+e] = coef * sum_d q[l,d] * Zscan[l,d,e] ----------------
__global__ void ctxt_kernel() {
    const int l = blockIdx.x, head = blockIdx.y;
    const int e = threadIdx.x;  // 64
    __shared__ float qs[64];
    qs[e] = g_q[l * 512 + head * 64 + e];
    __syncthreads();
    size_t base = (size_t)head * (L_ * 4096) + (size_t)l * 4096 + e;
    float acc = 0.0f;
    #pragma unroll 8
    for (int d = 0; d < 64; d++)
        acc += qs[d] * g_gz[base + (size_t)d * 64];
    g_ctxt[l * 512 + head * 64 + e] = acc * g_coef[head * L_ + l];
}

// ---------------- launch ----------------
extern "C" void kernel_launch(void* const* d_in, const int* in_sizes, int n_in,
                              void* d_out, int out_size) {
    const float* x   = (const float*)d_in[0];
    const float* Wq  = (const float*)d_in[1];
    const float* bq  = (const float*)d_in[2];
    const float* Wk  = (const float*)d_in[3];
    const float* bk  = (const float*)d_in[4];
    const float* Wv  = (const float*)d_in[5];
    const float* bv  = (const float*)d_in[6];
    const float* Wo  = (const float*)d_in[7];
    const float* bo  = (const float*)d_in[8];
    const float* Wg  = (const float*)d_in[9];
    const float* bg  = (const float*)d_in[10];
    const float* kvs = (const float*)d_in[11];
    const float* qks = (const float*)d_in[12];
    const float* flt = (const float*)d_in[13];
    float* out = (float*)d_out;

    void *pq, *pk, *pv, *pctxt;
    cudaGetSymbolAddress(&pq, g_q);
    cudaGetSymbolAddress(&pk, g_k);
    cudaGetSymbolAddress(&pv, g_v);
    cudaGetSymbolAddress(&pctxt, g_ctxt);

    dim3 gblk(16, 16);
    dim3 ggrid(D_ / 64, L_ / 64);

    sgemm_bias_kernel<<<ggrid, gblk>>>(x, Wq, bq, (float*)pq);
    sgemm_bias_kernel<<<ggrid, gblk>>>(x, Wk, bk, (float*)pk);
    sgemm_bias_kernel<<<ggrid, gblk>>>(x, Wv, bv, (float*)pv);

    norm_sim_kernel<<<L_, 512>>>(qks);

    conv_kernel<<<dim3(D_ / 64, L_ / 64, 2 * KF_), gblk>>>(flt);

    zgate_kernel<<<dim3(L_, H_), 256>>>(Wg, bg, kvs);

    scan_kernel<<<1, 32>>>();

    cumsum_kernel<<<dim3(16, H_), 256>>>();

    ctxt_kernel<<<dim3(L_, H_), 64>>>();

    sgemm_bias_kernel<<<ggrid, gblk>>>((const float*)pctxt, Wo, bo, out);
}

// round 5
// speedup vs baseline: 1.6671x; 1.6671x over previous
#include <cuda_runtime.h>
#include <cuda_bf16.h>
#include <math.h>
#include <stdint.h>

#define L_   1024
#define D_   512
#define H_   8
#define HD_  64
#define KF_  24
#define EPSF 1e-5f

// ---------------- static scratch ----------------
__device__ float g_q[L_ * D_];
__device__ float g_k[L_ * D_];
__device__ float g_v[L_ * D_];
__device__ float g_ck[(size_t)KF_ * L_ * D_];   // conv(k_norm): [kf][l][c]
__device__ float g_cv[(size_t)KF_ * L_ * D_];   // conv(v_norm)
__device__ float g_gz[(size_t)H_ * L_ * HD_ * HD_];
__device__ float g_sim[H_ * L_];
__device__ float g_gate[H_ * L_];
__device__ float g_coef[H_ * L_];
__device__ float g_ctxt[L_ * D_];

// bf16 split inputs for tensor-core conv
__device__ __nv_bfloat16 g_uT_hi[1024 * 1024];   // [c (k:0-511, v:512-1023)][t]
__device__ __nv_bfloat16 g_uT_lo[1024 * 1024];
__device__ __nv_bfloat16 g_fpad[2 * KF_ * 2048]; // [hi/lo][kf][1023 + lag], zero outside [1023,2046]

// ---------------- mma.sync bf16 ----------------
__device__ __forceinline__ void mma16816(float* c, const uint32_t* a, const uint32_t* b) {
    asm volatile(
        "mma.sync.aligned.m16n8k16.row.col.f32.bf16.bf16.f32 "
        "{%0,%1,%2,%3}, {%4,%5,%6,%7}, {%8,%9}, {%0,%1,%2,%3};"
        : "+f"(c[0]), "+f"(c[1]), "+f"(c[2]), "+f"(c[3])
        : "r"(a[0]), "r"(a[1]), "r"(a[2]), "r"(a[3]), "r"(b[0]), "r"(b[1]));
}

// ---------------- SGEMM (fp32, 64x64 tile) ----------------
__global__ void sgemm_bias_kernel(const float* __restrict__ A,
                                  const float* __restrict__ B,
                                  const float* __restrict__ bias,
                                  float* __restrict__ C) {
    __shared__ float As[64][17];
    __shared__ float Bs[16][64];
    const int tx = threadIdx.x, ty = threadIdx.y;
    const int tid = ty * 16 + tx;
    const int m0 = blockIdx.y * 64, n0 = blockIdx.x * 64;

    float acc[4][4] = {};
    for (int k0 = 0; k0 < 512; k0 += 16) {
        #pragma unroll
        for (int it = 0; it < 4; it++) {
            int e = tid + 256 * it;
            As[e >> 4][e & 15] = A[(m0 + (e >> 4)) * 512 + k0 + (e & 15)];
            Bs[e >> 6][e & 63] = B[(k0 + (e >> 6)) * 512 + n0 + (e & 63)];
        }
        __syncthreads();
        #pragma unroll
        for (int kk = 0; kk < 16; kk++) {
            float a[4], b[4];
            #pragma unroll
            for (int i = 0; i < 4; i++) a[i] = As[ty * 4 + i][kk];
            #pragma unroll
            for (int j = 0; j < 4; j++) b[j] = Bs[kk][tx * 4 + j];
            #pragma unroll
            for (int i = 0; i < 4; i++)
                #pragma unroll
                for (int j = 0; j < 4; j++)
                    acc[i][j] += a[i] * b[j];
        }
        __syncthreads();
    }
    #pragma unroll
    for (int i = 0; i < 4; i++)
        #pragma unroll
        for (int j = 0; j < 4; j++)
            C[(m0 + ty * 4 + i) * 512 + n0 + tx * 4 + j] = acc[i][j] + bias[n0 + tx * 4 + j];
}

// ---------------- sim + in-place L2 norm ----------------
__global__ void norm_sim_kernel(const float* __restrict__ qk_scale) {
    const int l = blockIdx.x;
    const int c = threadIdx.x;
    const int head = c >> 6, d = c & 63;
    float q = g_q[l * 512 + c];
    float k = g_k[l * 512 + c];
    float v = g_v[l * 512 + c];

    __shared__ float sd[512], sk[512], sv[512];
    sd[c] = q * k; sk[c] = k * k; sv[c] = v * v;
    __syncthreads();
    for (int off = 32; off >= 1; off >>= 1) {
        if (d < off) {
            sd[c] += sd[c + off];
            sk[c] += sk[c + off];
            sv[c] += sv[c + off];
        }
        __syncthreads();
    }
    float nk = fmaxf(sqrtf(sk[head * 64]), 1e-12f);
    float nv = fmaxf(sqrtf(sv[head * 64]), 1e-12f);
    g_k[l * 512 + c] = k / nk;
    g_v[l * 512 + c] = v / nv;
    if (d == 0) g_sim[head * L_ + l] = sd[head * 64] * qk_scale[head];
}

// ---------------- prep: transpose + bf16 hi/lo split of normalized k,v ----------------
__global__ void prep_split_kernel() {
    __shared__ float tile[32][33];
    const int t0 = blockIdx.x * 32, c0 = blockIdx.y * 32, z = blockIdx.z;
    const float* __restrict__ src = z ? g_v : g_k;
    const int tx = threadIdx.x, ty = threadIdx.y;
    #pragma unroll
    for (int kk = 0; kk < 4; kk++) {
        int i = ty + 8 * kk;
        tile[i][tx] = src[(t0 + i) * 512 + c0 + tx];
    }
    __syncthreads();
    const int rb = z * 512;
    #pragma unroll
    for (int kk = 0; kk < 4; kk++) {
        int i = ty + 8 * kk;
        float v = tile[tx][i];
        __nv_bfloat16 hi = __float2bfloat16_rn(v);
        __nv_bfloat16 lo = __float2bfloat16_rn(v - __bfloat162float(hi));
        size_t idx = (size_t)(rb + c0 + i) * 1024 + t0 + tx;
        g_uT_hi[idx] = hi;
        g_uT_lo[idx] = lo;
    }
}

// ---------------- prep: padded filters bf16 hi/lo, layout [kf][1023+lag] ----------------
__global__ void prep_filters_kernel(const float* __restrict__ flt) {
    int idx = blockIdx.x * 1024 + threadIdx.x;  // over 24*2048
    if (idx >= KF_ * 2048) return;
    int kf = idx >> 11, d = idx & 2047;
    float v = 0.0f;
    if (d >= 1023 && d < 2047) v = flt[(d - 1023) * KF_ + kf];
    __nv_bfloat16 hi = __float2bfloat16_rn(v);
    __nv_bfloat16 lo = __float2bfloat16_rn(v - __bfloat162float(hi));
    g_fpad[idx] = hi;
    g_fpad[KF_ * 2048 + idx] = lo;
}

// ---------------- HMMA conv: out[kf][l][c] = sum_t f[l-t,kf] u[t][c] ----------------
// Block tile: 128(l) x 128(c), K-chunks of 32 over t. 8 warps, warp tile 32x64.
// AS_STRIDE = 40 bf16 -> 80-byte rows (16B aligned for uint4 staging, conflict-free frag loads)
#define AS_STRIDE 40

__global__ void __launch_bounds__(256) conv_mma_kernel() {
    __shared__ __nv_bfloat16 As[2][128][AS_STRIDE];   // [split][l][t']
    __shared__ __nv_bfloat16 Bs[2][128][AS_STRIDE];   // [split][c][t']
    __shared__ __nv_bfloat16 fw[2][160];

    const int tid = threadIdx.x;
    const int wid = tid >> 5, lane = tid & 31;
    const int g = lane >> 2, tg = lane & 3;
    const int wm = (wid & 3) * 32;      // warp m offset
    const int wn = (wid >> 2) * 64;     // warp n offset

    const int c0 = blockIdx.x * 128;    // 0..1023 (k then v)
    const int l0 = blockIdx.y * 128;
    const int kf = blockIdx.z;

    const __nv_bfloat16* __restrict__ fp_hi = g_fpad + (size_t)kf * 2048;
    const __nv_bfloat16* __restrict__ fp_lo = g_fpad + (size_t)(KF_ + kf) * 2048;

    float acc[2][8][4] = {};

    const int tmax = l0 + 128;
    for (int t0 = 0; t0 < tmax; t0 += 32) {
        // filter window: d = 1023 + (l0+l) - (t0+tp), dmin at l=0,tp=31
        int dmin = 1023 + (l0 - t0) - 31;
        if (tid < 160) {
            fw[0][tid] = fp_hi[dmin + tid];
            fw[1][tid] = fp_lo[dmin + tid];
        }
        __syncthreads();
        // build A tiles: As[s][l][tp] = fw[s][l - tp + 31]
        #pragma unroll
        for (int it = 0; it < 16; it++) {
            int idx = tid + 256 * it;          // 4096
            int l = idx >> 5, tp = idx & 31;
            int w = l - tp + 31;
            As[0][l][tp] = fw[0][w];
            As[1][l][tp] = fw[1][w];
        }
        // build B tiles: Bs[s][c][tp] = uT[(c0+c)*1024 + t0 + tp]
        #pragma unroll
        for (int it = 0; it < 2; it++) {
            int cidx = tid + 256 * it;         // 512 chunks of 8 bf16
            int c = cidx >> 2, qq = cidx & 3;
            size_t goff = (size_t)(c0 + c) * 1024 + t0 + qq * 8;
            *(uint4*)&Bs[0][c][qq * 8] = *(const uint4*)(g_uT_hi + goff);
            *(uint4*)&Bs[1][c][qq * 8] = *(const uint4*)(g_uT_lo + goff);
        }
        __syncthreads();

        #pragma unroll
        for (int ks = 0; ks < 2; ks++) {
            const int kb = ks * 16;
            // A fragments: [split][mtile][4]
            uint32_t afr[2][2][4];
            #pragma unroll
            for (int s = 0; s < 2; s++)
                #pragma unroll
                for (int i = 0; i < 2; i++) {
                    int r = wm + i * 16 + g;
                    int cbase = kb + tg * 2;
                    afr[s][i][0] = *(const uint32_t*)&As[s][r][cbase];
                    afr[s][i][1] = *(const uint32_t*)&As[s][r + 8][cbase];
                    afr[s][i][2] = *(const uint32_t*)&As[s][r][cbase + 8];
                    afr[s][i][3] = *(const uint32_t*)&As[s][r + 8][cbase + 8];
                }
            #pragma unroll
            for (int j = 0; j < 8; j++) {
                int cc = wn + j * 8 + g;
                uint32_t bh[2], bl[2];
                bh[0] = *(const uint32_t*)&Bs[0][cc][kb + tg * 2];
                bh[1] = *(const uint32_t*)&Bs[0][cc][kb + tg * 2 + 8];
                bl[0] = *(const uint32_t*)&Bs[1][cc][kb + tg * 2];
                bl[1] = *(const uint32_t*)&Bs[1][cc][kb + tg * 2 + 8];
                #pragma unroll
                for (int i = 0; i < 2; i++) {
                    mma16816(acc[i][j], afr[0][i], bh);   // hi*hi
                    mma16816(acc[i][j], afr[0][i], bl);   // hi*lo
                    mma16816(acc[i][j], afr[1][i], bh);   // lo*hi
                }
            }
        }
        __syncthreads();
    }

    // writeback
    float* __restrict__ base = (c0 < 512) ? g_ck : g_cv;
    const int cb0 = (c0 < 512) ? c0 : c0 - 512;
    #pragma unroll
    for (int i = 0; i < 2; i++) {
        int r = l0 + wm + i * 16 + g;
        #pragma unroll
        for (int j = 0; j < 8; j++) {
            int cc = cb0 + wn + j * 8 + tg * 2;
            size_t o0 = ((size_t)kf * 1024 + r) * 512 + cc;
            size_t o1 = ((size_t)kf * 1024 + r + 8) * 512 + cc;
            *(float2*)(base + o0) = make_float2(acc[i][j][0], acc[i][j][1]);
            *(float2*)(base + o1) = make_float2(acc[i][j][2], acc[i][j][3]);
        }
    }
}

// ---------------- Z = sum_kf v~ (x) k~, gate, write gated Z ----------------
__global__ void zgate_kernel(const float* __restrict__ Wg,
                             const float* __restrict__ bg,
                             const float* __restrict__ kvscale) {
    const int l = blockIdx.x, head = blockIdx.y;
    const int tid = threadIdx.x;   // 256

    __shared__ float kt[KF_ * 64];
    __shared__ float vt[KF_ * 64];
    for (int e = tid; e < KF_ * 64; e += 256) {
        int kf = e >> 6, d = e & 63;
        size_t base = (size_t)kf * (L_ * D_) + (size_t)l * 512 + head * 64 + d;
        kt[e] = g_ck[base];
        vt[e] = g_cv[base];
    }
    __syncthreads();

    const int e = tid & 63;
    const int dg = tid >> 6;      // 0..3

    float kreg[KF_];
    #pragma unroll
    for (int kf = 0; kf < KF_; kf++) kreg[kf] = kt[kf * 64 + e];

    float acc[16];
    float lp = 0.0f;
    #pragma unroll
    for (int r = 0; r < 16; r++) {
        int d = dg * 16 + r;
        float s = 0.0f;
        #pragma unroll
        for (int kf = 0; kf < KF_; kf++)
            s += vt[kf * 64 + d] * kreg[kf];
        int m = d * 64 + e;
        s *= kvscale[head * 4096 + m];
        acc[r] = s;
        lp += s * Wg[m];
    }

    __shared__ float red[256];
    red[tid] = lp;
    __syncthreads();
    for (int off = 128; off >= 1; off >>= 1) {
        if (tid < off) red[tid] += red[tid + off];
        __syncthreads();
    }
    float logit = red[0] + bg[0];
    float rl = fmaxf(logit, 0.0f);
    float gate = rl * rl + EPSF;
    if (tid == 0) g_gate[head * L_ + l] = gate;

    size_t ob = (size_t)head * (L_ * 4096) + (size_t)l * 4096;
    #pragma unroll
    for (int r = 0; r < 16; r++)
        g_gz[ob + (size_t)(dg * 16 + r) * 64 + e] = gate * acc[r];
}

// ---------------- parallel scan: online softmax (m,s) + gate cumsum -> coef ----------------
__global__ void coef_kernel() {
    const int head = blockIdx.x;
    const int i = threadIdx.x;   // 1024
    __shared__ float sm[1024], ss[1024], sg[1024];
    float si = g_sim[head * L_ + i];
    sm[i] = si; ss[i] = 1.0f; sg[i] = g_gate[head * L_ + i];
    __syncthreads();
    for (int off = 1; off < 1024; off <<= 1) {
        float mp = 0.f, sp = 0.f, gp = 0.f;
        bool has = (i >= off);
        if (has) { mp = sm[i - off]; sp = ss[i - off]; gp = sg[i - off]; }
        __syncthreads();
        if (has) {
            float mi = sm[i], s_i = ss[i];
            float mn = fmaxf(mp, mi);
            ss[i] = sp * __expf(mp - mn) + s_i * __expf(mi - mn);
            sm[i] = mn;
            sg[i] += gp;
        }
        __syncthreads();
    }
    float w = __expf(si - sm[i]) / (ss[i] + EPSF);
    float silu = w / (1.0f + __expf(-w));
    g_coef[head * L_ + i] = (1.0f + silu) / (sg[i] + EPSF);
}

// ---------------- in-place cumsum of gated Z over l ----------------
__global__ void cumsum_kernel() {
    const int head = blockIdx.y;
    const int c = blockIdx.x * 256 + threadIdx.x;   // 0..4095
    size_t base = (size_t)head * (L_ * 4096) + c;
    float acc = 0.0f;
    for (int l0 = 0; l0 < L_; l0 += 8) {
        float v[8];
        #pragma unroll
        for (int i = 0; i < 8; i++) v[i] = g_gz[base + (size_t)(l0 + i) * 4096];
        #pragma unroll
        for (int i = 0; i < 8; i++) { acc += v[i]; v[i] = acc; }
        #pragma unroll
        for (int i = 0; i < 8; i++) g_gz[base + (size_t)(l0 + i) * 4096] = v[i];
    }
}

// ---------------- ctxt ----------------
__global__ void ctxt_kernel() {
    const int l = blockIdx.x, head = blockIdx.y;
    const int e = threadIdx.x;  // 64
    __shared__ float qs[64];
    qs[e] = g_q[l * 512 + head * 64 + e];
    __syncthreads();
    size_t base = (size_t)head * (L_ * 4096) + (size_t)l * 4096 + e;
    float acc = 0.0f;
    #pragma unroll 8
    for (int d = 0; d < 64; d++)
        acc += qs[d] * g_gz[base + (size_t)d * 64];
    g_ctxt[l * 512 + head * 64 + e] = acc * g_coef[head * L_ + l];
}

// ---------------- launch ----------------
extern "C" void kernel_launch(void* const* d_in, const int* in_sizes, int n_in,
                              void* d_out, int out_size) {
    const float* x   = (const float*)d_in[0];
    const float* Wq  = (const float*)d_in[1];
    const float* bq  = (const float*)d_in[2];
    const float* Wk  = (const float*)d_in[3];
    const float* bk  = (const float*)d_in[4];
    const float* Wv  = (const float*)d_in[5];
    const float* bv  = (const float*)d_in[6];
    const float* Wo  = (const float*)d_in[7];
    const float* bo  = (const float*)d_in[8];
    const float* Wg  = (const float*)d_in[9];
    const float* bg  = (const float*)d_in[10];
    const float* kvs = (const float*)d_in[11];
    const float* qks = (const float*)d_in[12];
    const float* flt = (const float*)d_in[13];
    float* out = (float*)d_out;

    void *pq, *pk, *pv, *pctxt;
    cudaGetSymbolAddress(&pq, g_q);
    cudaGetSymbolAddress(&pk, g_k);
    cudaGetSymbolAddress(&pv, g_v);
    cudaGetSymbolAddress(&pctxt, g_ctxt);

    dim3 gblk(16, 16);
    dim3 ggrid(D_ / 64, L_ / 64);

    sgemm_bias_kernel<<<ggrid, gblk>>>(x, Wq, bq, (float*)pq);
    sgemm_bias_kernel<<<ggrid, gblk>>>(x, Wk, bk, (float*)pk);
    sgemm_bias_kernel<<<ggrid, gblk>>>(x, Wv, bv, (float*)pv);

    norm_sim_kernel<<<L_, 512>>>(qks);

    prep_split_kernel<<<dim3(32, 16, 2), dim3(32, 8)>>>();
    prep_filters_kernel<<<48, 1024>>>(flt);

    conv_mma_kernel<<<dim3(8, 8, 24), 256>>>();

    zgate_kernel<<<dim3(L_, H_), 256>>>(Wg, bg, kvs);

    coef_kernel<<<H_, 1024>>>();

    cumsum_kernel<<<dim3(16, H_), 256>>>();

    ctxt_kernel<<<dim3(L_, H_), 64>>>();

    sgemm_bias_kernel<<<ggrid, gblk>>>((const float*)pctxt, Wo, bo, out);
}

// round 6
// speedup vs baseline: 2.1867x; 1.3117x over previous
#include <cuda_runtime.h>
#include <cuda_bf16.h>
#include <math.h>
#include <stdint.h>

#define L_   1024
#define D_   512
#define H_   8
#define HD_  64
#define KF_  24
#define EPSF 1e-5f

// ---------------- static scratch ----------------
__device__ float g_q[L_ * D_];
__device__ float g_k[L_ * D_];
__device__ float g_v[L_ * D_];
__device__ float g_ck[(size_t)KF_ * L_ * D_];   // conv(k_norm): [kf][l][c]
__device__ float g_cv[(size_t)KF_ * L_ * D_];   // conv(v_norm)
__device__ float g_gz[(size_t)H_ * L_ * HD_ * HD_];
__device__ float g_sim[H_ * L_];
__device__ float g_gate[H_ * L_];
__device__ float g_coef[H_ * L_];
__device__ float g_ctxt[L_ * D_];

// bf16 split inputs for tensor-core conv
__device__ __nv_bfloat16 g_uT_hi[1024 * 1024];   // [c (k:0-511, v:512-1023)][t]
__device__ __nv_bfloat16 g_uT_lo[1024 * 1024];
__device__ __nv_bfloat16 g_fpad[2 * KF_ * 2048]; // [hi/lo][kf][1023 + lag], zero outside [1023,2046]

// ---------------- mma.sync bf16 ----------------
__device__ __forceinline__ void mma16816(float* c, const uint32_t* a, const uint32_t* b) {
    asm volatile(
        "mma.sync.aligned.m16n8k16.row.col.f32.bf16.bf16.f32 "
        "{%0,%1,%2,%3}, {%4,%5,%6,%7}, {%8,%9}, {%0,%1,%2,%3};"
        : "+f"(c[0]), "+f"(c[1]), "+f"(c[2]), "+f"(c[3])
        : "r"(a[0]), "r"(a[1]), "r"(a[2]), "r"(a[3]), "r"(b[0]), "r"(b[1]));
}

__device__ __forceinline__ void cp_async16(uint32_t saddr, const void* gptr) {
    asm volatile("cp.async.cg.shared.global [%0], [%1], 16;" :: "r"(saddr), "l"(gptr));
}
#define CP_COMMIT() asm volatile("cp.async.commit_group;" ::: "memory")
#define CP_WAIT0()  asm volatile("cp.async.wait_group 0;" ::: "memory")

// ---------------- fused QKV SGEMM (fp32, 64x64 tile, z selects Wq/Wk/Wv) ----------------
__global__ void qkv_gemm_kernel(const float* __restrict__ A,
                                const float* __restrict__ Wq, const float* __restrict__ Wk,
                                const float* __restrict__ Wv,
                                const float* __restrict__ bq, const float* __restrict__ bk,
                                const float* __restrict__ bv) {
    __shared__ float As[64][17];
    __shared__ float Bs[16][64];
    const int tx = threadIdx.x, ty = threadIdx.y;
    const int tid = ty * 16 + tx;
    const int m0 = blockIdx.y * 64, n0 = blockIdx.x * 64;

    const float* B; const float* bias; float* C;
    if (blockIdx.z == 0)      { B = Wq; bias = bq; C = g_q; }
    else if (blockIdx.z == 1) { B = Wk; bias = bk; C = g_k; }
    else                      { B = Wv; bias = bv; C = g_v; }

    float acc[4][4] = {};
    for (int k0 = 0; k0 < 512; k0 += 16) {
        #pragma unroll
        for (int it = 0; it < 4; it++) {
            int e = tid + 256 * it;
            As[e >> 4][e & 15] = A[(m0 + (e >> 4)) * 512 + k0 + (e & 15)];
            Bs[e >> 6][e & 63] = B[(k0 + (e >> 6)) * 512 + n0 + (e & 63)];
        }
        __syncthreads();
        #pragma unroll
        for (int kk = 0; kk < 16; kk++) {
            float a[4], b[4];
            #pragma unroll
            for (int i = 0; i < 4; i++) a[i] = As[ty * 4 + i][kk];
            #pragma unroll
            for (int j = 0; j < 4; j++) b[j] = Bs[kk][tx * 4 + j];
            #pragma unroll
            for (int i = 0; i < 4; i++)
                #pragma unroll
                for (int j = 0; j < 4; j++)
                    acc[i][j] += a[i] * b[j];
        }
        __syncthreads();
    }
    #pragma unroll
    for (int i = 0; i < 4; i++)
        #pragma unroll
        for (int j = 0; j < 4; j++)
            C[(m0 + ty * 4 + i) * 512 + n0 + tx * 4 + j] = acc[i][j] + bias[n0 + tx * 4 + j];
}

// ---------------- plain SGEMM for the output projection ----------------
__global__ void sgemm_bias_kernel(const float* __restrict__ A,
                                  const float* __restrict__ B,
                                  const float* __restrict__ bias,
                                  float* __restrict__ C) {
    __shared__ float As[64][17];
    __shared__ float Bs[16][64];
    const int tx = threadIdx.x, ty = threadIdx.y;
    const int tid = ty * 16 + tx;
    const int m0 = blockIdx.y * 64, n0 = blockIdx.x * 64;

    float acc[4][4] = {};
    for (int k0 = 0; k0 < 512; k0 += 16) {
        #pragma unroll
        for (int it = 0; it < 4; it++) {
            int e = tid + 256 * it;
            As[e >> 4][e & 15] = A[(m0 + (e >> 4)) * 512 + k0 + (e & 15)];
            Bs[e >> 6][e & 63] = B[(k0 + (e >> 6)) * 512 + n0 + (e & 63)];
        }
        __syncthreads();
        #pragma unroll
        for (int kk = 0; kk < 16; kk++) {
            float a[4], b[4];
            #pragma unroll
            for (int i = 0; i < 4; i++) a[i] = As[ty * 4 + i][kk];
            #pragma unroll
            for (int j = 0; j < 4; j++) b[j] = Bs[kk][tx * 4 + j];
            #pragma unroll
            for (int i = 0; i < 4; i++)
                #pragma unroll
                for (int j = 0; j < 4; j++)
                    acc[i][j] += a[i] * b[j];
        }
        __syncthreads();
    }
    #pragma unroll
    for (int i = 0; i < 4; i++)
        #pragma unroll
        for (int j = 0; j < 4; j++)
            C[(m0 + ty * 4 + i) * 512 + n0 + tx * 4 + j] = acc[i][j] + bias[n0 + tx * 4 + j];
}

// ---------------- sim + in-place L2 norm ----------------
__global__ void norm_sim_kernel(const float* __restrict__ qk_scale) {
    const int l = blockIdx.x;
    const int c = threadIdx.x;
    const int head = c >> 6, d = c & 63;
    float q = g_q[l * 512 + c];
    float k = g_k[l * 512 + c];
    float v = g_v[l * 512 + c];

    __shared__ float sd[512], sk[512], sv[512];
    sd[c] = q * k; sk[c] = k * k; sv[c] = v * v;
    __syncthreads();
    for (int off = 32; off >= 1; off >>= 1) {
        if (d < off) {
            sd[c] += sd[c + off];
            sk[c] += sk[c + off];
            sv[c] += sv[c + off];
        }
        __syncthreads();
    }
    float nk = fmaxf(sqrtf(sk[head * 64]), 1e-12f);
    float nv = fmaxf(sqrtf(sv[head * 64]), 1e-12f);
    g_k[l * 512 + c] = k / nk;
    g_v[l * 512 + c] = v / nv;
    if (d == 0) g_sim[head * L_ + l] = sd[head * 64] * qk_scale[head];
}

// ---------------- prep: transpose + bf16 hi/lo split of normalized k,v ----------------
__global__ void prep_split_kernel() {
    __shared__ float tile[32][33];
    const int t0 = blockIdx.x * 32, c0 = blockIdx.y * 32, z = blockIdx.z;
    const float* __restrict__ src = z ? g_v : g_k;
    const int tx = threadIdx.x, ty = threadIdx.y;
    #pragma unroll
    for (int kk = 0; kk < 4; kk++) {
        int i = ty + 8 * kk;
        tile[i][tx] = src[(t0 + i) * 512 + c0 + tx];
    }
    __syncthreads();
    const int rb = z * 512;
    #pragma unroll
    for (int kk = 0; kk < 4; kk++) {
        int i = ty + 8 * kk;
        float v = tile[tx][i];
        __nv_bfloat16 hi = __float2bfloat16_rn(v);
        __nv_bfloat16 lo = __float2bfloat16_rn(v - __bfloat162float(hi));
        size_t idx = (size_t)(rb + c0 + i) * 1024 + t0 + tx;
        g_uT_hi[idx] = hi;
        g_uT_lo[idx] = lo;
    }
}

// ---------------- prep: padded filters bf16 hi/lo, layout [kf][1023+lag] ----------------
__global__ void prep_filters_kernel(const float* __restrict__ flt) {
    int idx = blockIdx.x * 1024 + threadIdx.x;  // over 24*2048
    if (idx >= KF_ * 2048) return;
    int kf = idx >> 11, d = idx & 2047;
    float v = 0.0f;
    if (d >= 1023 && d < 2047) v = flt[(d - 1023) * KF_ + kf];
    __nv_bfloat16 hi = __float2bfloat16_rn(v);
    __nv_bfloat16 lo = __float2bfloat16_rn(v - __bfloat162float(hi));
    g_fpad[idx] = hi;
    g_fpad[KF_ * 2048 + idx] = lo;
}

// ---------------- HMMA conv: out[kf][l][c] = sum_t f[l-t,kf] u[t][c] ----------------
// Toeplitz A fragments built directly from a packed 160-entry filter window (no A tile).
// B tiles double-buffered via cp.async. Block 128(l)x128(c), K-chunks of 32, 8 warps.
#define BS_STRIDE 40

__global__ void __launch_bounds__(256) conv_mma_kernel() {
    __shared__ __align__(16) __nv_bfloat16 Bs[2][2][128][BS_STRIDE]; // [buf][split][c][t']
    __shared__ uint32_t fwp[2][2][160];                              // [buf][split][x] = {f[x], f[x-1]}

    const int tid = threadIdx.x;
    const int wid = tid >> 5, lane = tid & 31;
    const int g = lane >> 2, tg = lane & 3;
    const int wm = (wid & 3) * 32;      // warp m offset
    const int wn = (wid >> 2) * 64;     // warp n offset

    const int c0 = blockIdx.x * 128;            // 0..1023 (k then v)
    const int l0 = (7 - blockIdx.y) * 128;      // longest blocks first
    const int kf = blockIdx.z;

    const __nv_bfloat16* __restrict__ fp_hi = g_fpad + (size_t)kf * 2048;
    const __nv_bfloat16* __restrict__ fp_lo = g_fpad + (size_t)(KF_ + kf) * 2048;

    const int nIter = (l0 + 128) >> 5;

    auto prefetch = [&](int it, int buf) {
        const int t0 = it << 5;
        #pragma unroll
        for (int r = 0; r < 4; r++) {
            int cidx = tid + 256 * r;            // 1024 chunks of 16B
            int split = cidx >> 9;
            int rem = cidx & 511;
            int c = rem >> 2, qq = rem & 3;
            const __nv_bfloat16* gsrc =
                (split ? g_uT_lo : g_uT_hi) + (size_t)(c0 + c) * 1024 + t0 + qq * 8;
            uint32_t saddr = (uint32_t)__cvta_generic_to_shared(&Bs[buf][split][c][qq * 8]);
            cp_async16(saddr, gsrc);
        }
        CP_COMMIT();
        if (tid < 160) {
            int dmin = 1023 + (l0 - t0) - 31;
            uint32_t h0 = (uint32_t)__bfloat16_as_ushort(fp_hi[dmin + tid]);
            uint32_t h1 = (uint32_t)__bfloat16_as_ushort(fp_hi[dmin + tid - 1]);
            fwp[buf][0][tid] = h0 | (h1 << 16);
            uint32_t lo0 = (uint32_t)__bfloat16_as_ushort(fp_lo[dmin + tid]);
            uint32_t lo1 = (uint32_t)__bfloat16_as_ushort(fp_lo[dmin + tid - 1]);
            fwp[buf][1][tid] = lo0 | (lo1 << 16);
        }
    };

    float acc[2][8][4] = {};

    prefetch(0, 0);
    CP_WAIT0();
    __syncthreads();

    for (int it = 0; it < nIter; it++) {
        const int buf = it & 1;
        if (it + 1 < nIter) prefetch(it + 1, buf ^ 1);

        #pragma unroll
        for (int ks = 0; ks < 2; ks++) {
            const int kb = ks * 16;
            uint32_t a0[2][2], a1[2][2], a2[2][2];   // fwp[x], fwp[x+8], fwp[x-8]
            #pragma unroll
            for (int s = 0; s < 2; s++)
                #pragma unroll
                for (int i = 0; i < 2; i++) {
                    int x = wm + i * 16 + g - (kb + tg * 2) + 31;
                    a0[s][i] = fwp[buf][s][x];
                    a1[s][i] = fwp[buf][s][x + 8];
                    a2[s][i] = fwp[buf][s][x - 8];
                }
            #pragma unroll
            for (int j = 0; j < 8; j++) {
                int cc = wn + j * 8 + g;
                uint32_t bh[2], bl[2];
                bh[0] = *(const uint32_t*)&Bs[buf][0][cc][kb + tg * 2];
                bh[1] = *(const uint32_t*)&Bs[buf][0][cc][kb + tg * 2 + 8];
                bl[0] = *(const uint32_t*)&Bs[buf][1][cc][kb + tg * 2];
                bl[1] = *(const uint32_t*)&Bs[buf][1][cc][kb + tg * 2 + 8];
                #pragma unroll
                for (int i = 0; i < 2; i++) {
                    uint32_t ah[4] = {a0[0][i], a1[0][i], a2[0][i], a0[0][i]};
                    uint32_t al[4] = {a0[1][i], a1[1][i], a2[1][i], a0[1][i]};
                    mma16816(acc[i][j], ah, bh);   // hi*hi
                    mma16816(acc[i][j], ah, bl);   // hi*lo
                    mma16816(acc[i][j], al, bh);   // lo*hi
                }
            }
        }
        if (it + 1 < nIter) CP_WAIT0();
        __syncthreads();
    }

    // writeback
    float* __restrict__ base = (c0 < 512) ? g_ck : g_cv;
    const int cb0 = (c0 < 512) ? c0 : c0 - 512;
    #pragma unroll
    for (int i = 0; i < 2; i++) {
        int r = l0 + wm + i * 16 + g;
        #pragma unroll
        for (int j = 0; j < 8; j++) {
            int cc = cb0 + wn + j * 8 + tg * 2;
            size_t o0 = ((size_t)kf * 1024 + r) * 512 + cc;
            size_t o1 = ((size_t)kf * 1024 + r + 8) * 512 + cc;
            *(float2*)(base + o0) = make_float2(acc[i][j][0], acc[i][j][1]);
            *(float2*)(base + o1) = make_float2(acc[i][j][2], acc[i][j][3]);
        }
    }
}

// ---------------- Z = sum_kf v~ (x) k~, gate, write gated Z ----------------
__global__ void zgate_kernel(const float* __restrict__ Wg,
                             const float* __restrict__ bg,
                             const float* __restrict__ kvscale) {
    const int l = blockIdx.x, head = blockIdx.y;
    const int tid = threadIdx.x;   // 256

    __shared__ float kt[KF_ * 64];
    __shared__ float vt[KF_ * 64];
    for (int e = tid; e < KF_ * 64; e += 256) {
        int kf = e >> 6, d = e & 63;
        size_t base = (size_t)kf * (L_ * D_) + (size_t)l * 512 + head * 64 + d;
        kt[e] = g_ck[base];
        vt[e] = g_cv[base];
    }
    __syncthreads();

    const int e = tid & 63;
    const int dg = tid >> 6;      // 0..3

    float kreg[KF_];
    #pragma unroll
    for (int kf = 0; kf < KF_; kf++) kreg[kf] = kt[kf * 64 + e];

    float acc[16];
    float lp = 0.0f;
    #pragma unroll
    for (int r = 0; r < 16; r++) {
        int d = dg * 16 + r;
        float s = 0.0f;
        #pragma unroll
        for (int kf = 0; kf < KF_; kf++)
            s += vt[kf * 64 + d] * kreg[kf];
        int m = d * 64 + e;
        s *= kvscale[head * 4096 + m];
        acc[r] = s;
        lp += s * Wg[m];
    }

    __shared__ float red[256];
    red[tid] = lp;
    __syncthreads();
    for (int off = 128; off >= 1; off >>= 1) {
        if (tid < off) red[tid] += red[tid + off];
        __syncthreads();
    }
    float logit = red[0] + bg[0];
    float rl = fmaxf(logit, 0.0f);
    float gate = rl * rl + EPSF;
    if (tid == 0) g_gate[head * L_ + l] = gate;

    size_t ob = (size_t)head * (L_ * 4096) + (size_t)l * 4096;
    #pragma unroll
    for (int r = 0; r < 16; r++)
        g_gz[ob + (size_t)(dg * 16 + r) * 64 + e] = gate * acc[r];
}

// ---------------- parallel scan: online softmax (m,s) + gate cumsum -> coef ----------------
__global__ void coef_kernel() {
    const int head = blockIdx.x;
    const int i = threadIdx.x;   // 1024
    __shared__ float sm[1024], ss[1024], sg[1024];
    float si = g_sim[head * L_ + i];
    sm[i] = si; ss[i] = 1.0f; sg[i] = g_gate[head * L_ + i];
    __syncthreads();
    for (int off = 1; off < 1024; off <<= 1) {
        float mp = 0.f, sp = 0.f, gp = 0.f;
        bool has = (i >= off);
        if (has) { mp = sm[i - off]; sp = ss[i - off]; gp = sg[i - off]; }
        __syncthreads();
        if (has) {
            float mi = sm[i], s_i = ss[i];
            float mn = fmaxf(mp, mi);
            ss[i] = sp * __expf(mp - mn) + s_i * __expf(mi - mn);
            sm[i] = mn;
            sg[i] += gp;
        }
        __syncthreads();
    }
    float w = __expf(si - sm[i]) / (ss[i] + EPSF);
    float silu = w / (1.0f + __expf(-w));
    g_coef[head * L_ + i] = (1.0f + silu) / (sg[i] + EPSF);
}

// ---------------- in-place cumsum of gated Z over l ----------------
__global__ void cumsum_kernel() {
    const int head = blockIdx.y;
    const int c = blockIdx.x * 256 + threadIdx.x;   // 0..4095
    size_t base = (size_t)head * (L_ * 4096) + c;
    float acc = 0.0f;
    for (int l0 = 0; l0 < L_; l0 += 8) {
        float v[8];
        #pragma unroll
        for (int i = 0; i < 8; i++) v[i] = g_gz[base + (size_t)(l0 + i) * 4096];
        #pragma unroll
        for (int i = 0; i < 8; i++) { acc += v[i]; v[i] = acc; }
        #pragma unroll
        for (int i = 0; i < 8; i++) g_gz[base + (size_t)(l0 + i) * 4096] = v[i];
    }
}

// ---------------- ctxt ----------------
__global__ void ctxt_kernel() {
    const int l = blockIdx.x, head = blockIdx.y;
    const int e = threadIdx.x;  // 64
    __shared__ float qs[64];
    qs[e] = g_q[l * 512 + head * 64 + e];
    __syncthreads();
    size_t base = (size_t)head * (L_ * 4096) + (size_t)l * 4096 + e;
    float acc = 0.0f;
    #pragma unroll 8
    for (int d = 0; d < 64; d++)
        acc += qs[d] * g_gz[base + (size_t)d * 64];
    g_ctxt[l * 512 + head * 64 + e] = acc * g_coef[head * L_ + l];
}

// ---------------- launch ----------------
extern "C" void kernel_launch(void* const* d_in, const int* in_sizes, int n_in,
                              void* d_out, int out_size) {
    const float* x   = (const float*)d_in[0];
    const float* Wq  = (const float*)d_in[1];
    const float* bq  = (const float*)d_in[2];
    const float* Wk  = (const float*)d_in[3];
    const float* bk  = (const float*)d_in[4];
    const float* Wv  = (const float*)d_in[5];
    const float* bv  = (const float*)d_in[6];
    const float* Wo  = (const float*)d_in[7];
    const float* bo  = (const float*)d_in[8];
    const float* Wg  = (const float*)d_in[9];
    const float* bg  = (const float*)d_in[10];
    const float* kvs = (const float*)d_in[11];
    const float* qks = (const float*)d_in[12];
    const float* flt = (const float*)d_in[13];
    float* out = (float*)d_out;

    void *pctxt;
    cudaGetSymbolAddress(&pctxt, g_ctxt);

    dim3 gblk(16, 16);

    qkv_gemm_kernel<<<dim3(8, 16, 3), gblk>>>(x, Wq, Wk, Wv, bq, bk, bv);

    norm_sim_kernel<<<L_, 512>>>(qks);

    prep_split_kernel<<<dim3(32, 16, 2), dim3(32, 8)>>>();
    prep_filters_kernel<<<48, 1024>>>(flt);

    conv_mma_kernel<<<dim3(8, 8, 24), 256>>>();

    zgate_kernel<<<dim3(L_, H_), 256>>>(Wg, bg, kvs);

    coef_kernel<<<H_, 1024>>>();

    cumsum_kernel<<<dim3(16, H_), 256>>>();

    ctxt_kernel<<<dim3(L_, H_), 64>>>();

    sgemm_bias_kernel<<<dim3(8, 16), gblk>>>((const float*)pctxt, Wo, bo, out);
}

// round 7
// speedup vs baseline: 2.3391x; 1.0697x over previous
#include <cuda_runtime.h>
#include <cuda_bf16.h>
#include <math.h>
#include <stdint.h>

#define L_   1024
#define D_   512
#define H_   8
#define HD_  64
#define KF_  24
#define EPSF 1e-5f
#define NCH  16
#define CL   64

// ---------------- static scratch ----------------
__device__ float g_q[L_ * D_];
__device__ float g_k[L_ * D_];
__device__ float g_v[L_ * D_];
__device__ float g_ck[(size_t)KF_ * L_ * D_];   // conv(k_norm): [kf][l][c]
__device__ float g_cv[(size_t)KF_ * L_ * D_];   // conv(v_norm)
__device__ float g_sim[H_ * L_];
__device__ float g_gate[H_ * L_];
__device__ float g_coef[H_ * L_];
__device__ float g_ctxt[L_ * D_];
__device__ float g_T[H_][NCH][4096];            // per-chunk gated-Z sums
__device__ float g_P[H_][NCH][4096];            // exclusive chunk prefix

// bf16 split inputs for tensor-core conv
__device__ __nv_bfloat16 g_uT_hi[1024 * 1024];   // [c (k:0-511, v:512-1023)][t]
__device__ __nv_bfloat16 g_uT_lo[1024 * 1024];
__device__ __nv_bfloat16 g_fpad[2 * KF_ * 2048]; // [hi/lo][kf][1023 + lag]

// ---------------- mma.sync bf16 ----------------
__device__ __forceinline__ void mma16816(float* c, const uint32_t* a, const uint32_t* b) {
    asm volatile(
        "mma.sync.aligned.m16n8k16.row.col.f32.bf16.bf16.f32 "
        "{%0,%1,%2,%3}, {%4,%5,%6,%7}, {%8,%9}, {%0,%1,%2,%3};"
        : "+f"(c[0]), "+f"(c[1]), "+f"(c[2]), "+f"(c[3])
        : "r"(a[0]), "r"(a[1]), "r"(a[2]), "r"(a[3]), "r"(b[0]), "r"(b[1]));
}

__device__ __forceinline__ void cp_async16(uint32_t saddr, const void* gptr) {
    asm volatile("cp.async.cg.shared.global [%0], [%1], 16;" :: "r"(saddr), "l"(gptr));
}
#define CP_COMMIT() asm volatile("cp.async.commit_group;" ::: "memory")
#define CP_WAIT0()  asm volatile("cp.async.wait_group 0;" ::: "memory")

// ---------------- fused QKV SGEMM ----------------
__global__ void qkv_gemm_kernel(const float* __restrict__ A,
                                const float* __restrict__ Wq, const float* __restrict__ Wk,
                                const float* __restrict__ Wv,
                                const float* __restrict__ bq, const float* __restrict__ bk,
                                const float* __restrict__ bv) {
    __shared__ float As[64][17];
    __shared__ float Bs[16][64];
    const int tx = threadIdx.x, ty = threadIdx.y;
    const int tid = ty * 16 + tx;
    const int m0 = blockIdx.y * 64, n0 = blockIdx.x * 64;

    const float* B; const float* bias; float* C;
    if (blockIdx.z == 0)      { B = Wq; bias = bq; C = g_q; }
    else if (blockIdx.z == 1) { B = Wk; bias = bk; C = g_k; }
    else                      { B = Wv; bias = bv; C = g_v; }

    float acc[4][4] = {};
    for (int k0 = 0; k0 < 512; k0 += 16) {
        #pragma unroll
        for (int it = 0; it < 4; it++) {
            int e = tid + 256 * it;
            As[e >> 4][e & 15] = A[(m0 + (e >> 4)) * 512 + k0 + (e & 15)];
            Bs[e >> 6][e & 63] = B[(k0 + (e >> 6)) * 512 + n0 + (e & 63)];
        }
        __syncthreads();
        #pragma unroll
        for (int kk = 0; kk < 16; kk++) {
            float a[4], b[4];
            #pragma unroll
            for (int i = 0; i < 4; i++) a[i] = As[ty * 4 + i][kk];
            #pragma unroll
            for (int j = 0; j < 4; j++) b[j] = Bs[kk][tx * 4 + j];
            #pragma unroll
            for (int i = 0; i < 4; i++)
                #pragma unroll
                for (int j = 0; j < 4; j++)
                    acc[i][j] += a[i] * b[j];
        }
        __syncthreads();
    }
    #pragma unroll
    for (int i = 0; i < 4; i++)
        #pragma unroll
        for (int j = 0; j < 4; j++)
            C[(m0 + ty * 4 + i) * 512 + n0 + tx * 4 + j] = acc[i][j] + bias[n0 + tx * 4 + j];
}

// ---------------- plain SGEMM for the output projection ----------------
__global__ void sgemm_bias_kernel(const float* __restrict__ A,
                                  const float* __restrict__ B,
                                  const float* __restrict__ bias,
                                  float* __restrict__ C) {
    __shared__ float As[64][17];
    __shared__ float Bs[16][64];
    const int tx = threadIdx.x, ty = threadIdx.y;
    const int tid = ty * 16 + tx;
    const int m0 = blockIdx.y * 64, n0 = blockIdx.x * 64;

    float acc[4][4] = {};
    for (int k0 = 0; k0 < 512; k0 += 16) {
        #pragma unroll
        for (int it = 0; it < 4; it++) {
            int e = tid + 256 * it;
            As[e >> 4][e & 15] = A[(m0 + (e >> 4)) * 512 + k0 + (e & 15)];
            Bs[e >> 6][e & 63] = B[(k0 + (e >> 6)) * 512 + n0 + (e & 63)];
        }
        __syncthreads();
        #pragma unroll
        for (int kk = 0; kk < 16; kk++) {
            float a[4], b[4];
            #pragma unroll
            for (int i = 0; i < 4; i++) a[i] = As[ty * 4 + i][kk];
            #pragma unroll
            for (int j = 0; j < 4; j++) b[j] = Bs[kk][tx * 4 + j];
            #pragma unroll
            for (int i = 0; i < 4; i++)
                #pragma unroll
                for (int j = 0; j < 4; j++)
                    acc[i][j] += a[i] * b[j];
        }
        __syncthreads();
    }
    #pragma unroll
    for (int i = 0; i < 4; i++)
        #pragma unroll
        for (int j = 0; j < 4; j++)
            C[(m0 + ty * 4 + i) * 512 + n0 + tx * 4 + j] = acc[i][j] + bias[n0 + tx * 4 + j];
}

// ---------------- sim + in-place L2 norm ----------------
__global__ void norm_sim_kernel(const float* __restrict__ qk_scale) {
    const int l = blockIdx.x;
    const int c = threadIdx.x;
    const int head = c >> 6, d = c & 63;
    float q = g_q[l * 512 + c];
    float k = g_k[l * 512 + c];
    float v = g_v[l * 512 + c];

    __shared__ float sd[512], sk[512], sv[512];
    sd[c] = q * k; sk[c] = k * k; sv[c] = v * v;
    __syncthreads();
    for (int off = 32; off >= 1; off >>= 1) {
        if (d < off) {
            sd[c] += sd[c + off];
            sk[c] += sk[c + off];
            sv[c] += sv[c + off];
        }
        __syncthreads();
    }
    float nk = fmaxf(sqrtf(sk[head * 64]), 1e-12f);
    float nv = fmaxf(sqrtf(sv[head * 64]), 1e-12f);
    g_k[l * 512 + c] = k / nk;
    g_v[l * 512 + c] = v / nv;
    if (d == 0) g_sim[head * L_ + l] = sd[head * 64] * qk_scale[head];
}

// ---------------- prep: transpose + bf16 hi/lo split of normalized k,v ----------------
__global__ void prep_split_kernel() {
    __shared__ float tile[32][33];
    const int t0 = blockIdx.x * 32, c0 = blockIdx.y * 32, z = blockIdx.z;
    const float* __restrict__ src = z ? g_v : g_k;
    const int tx = threadIdx.x, ty = threadIdx.y;
    #pragma unroll
    for (int kk = 0; kk < 4; kk++) {
        int i = ty + 8 * kk;
        tile[i][tx] = src[(t0 + i) * 512 + c0 + tx];
    }
    __syncthreads();
    const int rb = z * 512;
    #pragma unroll
    for (int kk = 0; kk < 4; kk++) {
        int i = ty + 8 * kk;
        float v = tile[tx][i];
        __nv_bfloat16 hi = __float2bfloat16_rn(v);
        __nv_bfloat16 lo = __float2bfloat16_rn(v - __bfloat162float(hi));
        size_t idx = (size_t)(rb + c0 + i) * 1024 + t0 + tx;
        g_uT_hi[idx] = hi;
        g_uT_lo[idx] = lo;
    }
}

// ---------------- prep: padded filters bf16 hi/lo ----------------
__global__ void prep_filters_kernel(const float* __restrict__ flt) {
    int idx = blockIdx.x * 1024 + threadIdx.x;  // over 24*2048
    if (idx >= KF_ * 2048) return;
    int kf = idx >> 11, d = idx & 2047;
    float v = 0.0f;
    if (d >= 1023 && d < 2047) v = flt[(d - 1023) * KF_ + kf];
    __nv_bfloat16 hi = __float2bfloat16_rn(v);
    __nv_bfloat16 lo = __float2bfloat16_rn(v - __bfloat162float(hi));
    g_fpad[idx] = hi;
    g_fpad[KF_ * 2048 + idx] = lo;
}

// ---------------- HMMA conv ----------------
#define BS_STRIDE 40

__global__ void __launch_bounds__(256) conv_mma_kernel() {
    __shared__ __align__(16) __nv_bfloat16 Bs[2][2][128][BS_STRIDE];
    __shared__ uint32_t fwp[2][2][160];

    const int tid = threadIdx.x;
    const int wid = tid >> 5, lane = tid & 31;
    const int g = lane >> 2, tg = lane & 3;
    const int wm = (wid & 3) * 32;
    const int wn = (wid >> 2) * 64;

    const int c0 = blockIdx.x * 128;
    const int l0 = (7 - blockIdx.y) * 128;
    const int kf = blockIdx.z;

    const __nv_bfloat16* __restrict__ fp_hi = g_fpad + (size_t)kf * 2048;
    const __nv_bfloat16* __restrict__ fp_lo = g_fpad + (size_t)(KF_ + kf) * 2048;

    const int nIter = (l0 + 128) >> 5;

    auto prefetch = [&](int it, int buf) {
        const int t0 = it << 5;
        #pragma unroll
        for (int r = 0; r < 4; r++) {
            int cidx = tid + 256 * r;
            int split = cidx >> 9;
            int rem = cidx & 511;
            int c = rem >> 2, qq = rem & 3;
            const __nv_bfloat16* gsrc =
                (split ? g_uT_lo : g_uT_hi) + (size_t)(c0 + c) * 1024 + t0 + qq * 8;
            uint32_t saddr = (uint32_t)__cvta_generic_to_shared(&Bs[buf][split][c][qq * 8]);
            cp_async16(saddr, gsrc);
        }
        CP_COMMIT();
        if (tid < 160) {
            int dmin = 1023 + (l0 - t0) - 31;
            uint32_t h0 = (uint32_t)__bfloat16_as_ushort(fp_hi[dmin + tid]);
            uint32_t h1 = (uint32_t)__bfloat16_as_ushort(fp_hi[dmin + tid - 1]);
            fwp[buf][0][tid] = h0 | (h1 << 16);
            uint32_t lo0 = (uint32_t)__bfloat16_as_ushort(fp_lo[dmin + tid]);
            uint32_t lo1 = (uint32_t)__bfloat16_as_ushort(fp_lo[dmin + tid - 1]);
            fwp[buf][1][tid] = lo0 | (lo1 << 16);
        }
    };

    float acc[2][8][4] = {};

    prefetch(0, 0);
    CP_WAIT0();
    __syncthreads();

    for (int it = 0; it < nIter; it++) {
        const int buf = it & 1;
        if (it + 1 < nIter) prefetch(it + 1, buf ^ 1);

        #pragma unroll
        for (int ks = 0; ks < 2; ks++) {
            const int kb = ks * 16;
            uint32_t a0[2][2], a1[2][2], a2[2][2];
            #pragma unroll
            for (int s = 0; s < 2; s++)
                #pragma unroll
                for (int i = 0; i < 2; i++) {
                    int x = wm + i * 16 + g - (kb + tg * 2) + 31;
                    a0[s][i] = fwp[buf][s][x];
                    a1[s][i] = fwp[buf][s][x + 8];
                    a2[s][i] = fwp[buf][s][x - 8];
                }
            #pragma unroll
            for (int j = 0; j < 8; j++) {
                int cc = wn + j * 8 + g;
                uint32_t bh[2], bl[2];
                bh[0] = *(const uint32_t*)&Bs[buf][0][cc][kb + tg * 2];
                bh[1] = *(const uint32_t*)&Bs[buf][0][cc][kb + tg * 2 + 8];
                bl[0] = *(const uint32_t*)&Bs[buf][1][cc][kb + tg * 2];
                bl[1] = *(const uint32_t*)&Bs[buf][1][cc][kb + tg * 2 + 8];
                #pragma unroll
                for (int i = 0; i < 2; i++) {
                    uint32_t ah[4] = {a0[0][i], a1[0][i], a2[0][i], a0[0][i]};
                    uint32_t al[4] = {a0[1][i], a1[1][i], a2[1][i], a0[1][i]};
                    mma16816(acc[i][j], ah, bh);
                    mma16816(acc[i][j], ah, bl);
                    mma16816(acc[i][j], al, bh);
                }
            }
        }
        if (it + 1 < nIter) CP_WAIT0();
        __syncthreads();
    }

    float* __restrict__ base = (c0 < 512) ? g_ck : g_cv;
    const int cb0 = (c0 < 512) ? c0 : c0 - 512;
    #pragma unroll
    for (int i = 0; i < 2; i++) {
        int r = l0 + wm + i * 16 + g;
        #pragma unroll
        for (int j = 0; j < 8; j++) {
            int cc = cb0 + wn + j * 8 + tg * 2;
            size_t o0 = ((size_t)kf * 1024 + r) * 512 + cc;
            size_t o1 = ((size_t)kf * 1024 + r + 8) * 512 + cc;
            *(float2*)(base + o0) = make_float2(acc[i][j][0], acc[i][j][1]);
            *(float2*)(base + o1) = make_float2(acc[i][j][2], acc[i][j][3]);
        }
    }
}

// ---------------- Pass A: per-chunk gated-Z totals + gates ----------------
// block = (chunk, head), 256 threads: thread (dg = tid>>6 owns d in [dg*16,..+16), e = tid&63)
__global__ void __launch_bounds__(256) zsum_kernel(const float* __restrict__ Wg,
                                                   const float* __restrict__ bg,
                                                   const float* __restrict__ kvscale) {
    const int chunk = blockIdx.x, head = blockIdx.y;
    const int tid = threadIdx.x;
    const int e = tid & 63, dg = tid >> 6;
    const int l0 = chunk * CL;

    __shared__ __align__(16) float st[2][48][64];   // rows 0..23 ck, 24..47 cv
    __shared__ float red[8];
    __shared__ float gsh;

    float scl[16], wg[16];
    #pragma unroll
    for (int r = 0; r < 16; r++) {
        int m = (dg * 16 + r) * 64 + e;
        scl[r] = kvscale[head * 4096 + m];
        wg[r] = Wg[m];
    }
    const float bgv = bg[0];

    auto stage = [&](int l, int buf) {
        for (int i = tid; i < 768; i += 256) {
            int row = i >> 4, ch = i & 15;
            const float* src = ((row < 24) ? (g_ck + (size_t)row * (L_ * D_))
                                           : (g_cv + (size_t)(row - 24) * (L_ * D_)))
                               + (size_t)l * 512 + head * 64 + ch * 4;
            cp_async16((uint32_t)__cvta_generic_to_shared(&st[buf][row][ch * 4]), src);
        }
        CP_COMMIT();
    };

    float S[16] = {};
    stage(l0, 0);

    for (int li = 0; li < CL; li++) {
        const int buf = li & 1;
        CP_WAIT0();
        __syncthreads();
        if (li + 1 < CL) stage(l0 + li + 1, buf ^ 1);

        float z[16] = {};
        #pragma unroll
        for (int kf = 0; kf < KF_; kf++) {
            float ktv = st[buf][kf][e];
            const float4* vp = (const float4*)&st[buf][24 + kf][dg * 16];
            float4 v0 = vp[0], v1 = vp[1], v2 = vp[2], v3 = vp[3];
            z[0] += v0.x * ktv;  z[1] += v0.y * ktv;  z[2] += v0.z * ktv;  z[3] += v0.w * ktv;
            z[4] += v1.x * ktv;  z[5] += v1.y * ktv;  z[6] += v1.z * ktv;  z[7] += v1.w * ktv;
            z[8] += v2.x * ktv;  z[9] += v2.y * ktv;  z[10] += v2.z * ktv; z[11] += v2.w * ktv;
            z[12] += v3.x * ktv; z[13] += v3.y * ktv; z[14] += v3.z * ktv; z[15] += v3.w * ktv;
        }
        float lp = 0.0f;
        #pragma unroll
        for (int r = 0; r < 16; r++) {
            z[r] *= scl[r];
            lp += z[r] * wg[r];
        }
        #pragma unroll
        for (int off = 16; off >= 1; off >>= 1)
            lp += __shfl_xor_sync(0xffffffffu, lp, off);
        if ((tid & 31) == 0) red[tid >> 5] = lp;
        __syncthreads();
        if (tid == 0) {
            float s = red[0] + red[1] + red[2] + red[3] + red[4] + red[5] + red[6] + red[7];
            float logit = s + bgv;
            float rl = fmaxf(logit, 0.0f);
            float gate = rl * rl + EPSF;
            gsh = gate;
            g_gate[head * L_ + l0 + li] = gate;
        }
        __syncthreads();
        float gate = gsh;
        #pragma unroll
        for (int r = 0; r < 16; r++) S[r] += gate * z[r];
    }

    #pragma unroll
    for (int r = 0; r < 16; r++)
        g_T[head][chunk][(dg * 16 + r) * 64 + e] = S[r];
}

// ---------------- Pass B: exclusive chunk prefix ----------------
__global__ void chunk_prefix_kernel() {
    const int head = blockIdx.y;
    const int comp = blockIdx.x * 256 + threadIdx.x;   // 0..4095
    float run = 0.0f;
    #pragma unroll
    for (int ch = 0; ch < NCH; ch++) {
        float t = g_T[head][ch][comp];
        g_P[head][ch][comp] = run;
        run += t;
    }
}

// ---------------- parallel scan: online softmax (m,s) + gate cumsum -> coef ----------------
__global__ void coef_kernel() {
    const int head = blockIdx.x;
    const int i = threadIdx.x;   // 1024
    __shared__ float sm[1024], ss[1024], sg[1024];
    float si = g_sim[head * L_ + i];
    sm[i] = si; ss[i] = 1.0f; sg[i] = g_gate[head * L_ + i];
    __syncthreads();
    for (int off = 1; off < 1024; off <<= 1) {
        float mp = 0.f, sp = 0.f, gp = 0.f;
        bool has = (i >= off);
        if (has) { mp = sm[i - off]; sp = ss[i - off]; gp = sg[i - off]; }
        __syncthreads();
        if (has) {
            float mi = sm[i], s_i = ss[i];
            float mn = fmaxf(mp, mi);
            ss[i] = sp * __expf(mp - mn) + s_i * __expf(mi - mn);
            sm[i] = mn;
            sg[i] += gp;
        }
        __syncthreads();
    }
    float w = __expf(si - sm[i]) / (ss[i] + EPSF);
    float silu = w / (1.0f + __expf(-w));
    g_coef[head * L_ + i] = (1.0f + silu) / (sg[i] + EPSF);
}

// ---------------- Pass C: running scan + q contraction -> ctxt ----------------
__global__ void __launch_bounds__(256) ctxt_scan_kernel(const float* __restrict__ kvscale) {
    const int chunk = blockIdx.x, head = blockIdx.y;
    const int tid = threadIdx.x;
    const int e = tid & 63, dg = tid >> 6;
    const int l0 = chunk * CL;

    __shared__ __align__(16) float st[2][49][64];   // rows 0..23 ck, 24..47 cv, 48 q
    __shared__ float red4[4][64];
    __shared__ float gt[CL], cf[CL];

    float scl[16];
    #pragma unroll
    for (int r = 0; r < 16; r++)
        scl[r] = kvscale[head * 4096 + (dg * 16 + r) * 64 + e];

    if (tid < CL) {
        gt[tid] = g_gate[head * L_ + l0 + tid];
        cf[tid] = g_coef[head * L_ + l0 + tid];
    }

    float S[16];
    #pragma unroll
    for (int r = 0; r < 16; r++)
        S[r] = g_P[head][chunk][(dg * 16 + r) * 64 + e];

    auto stage = [&](int l, int buf) {
        for (int i = tid; i < 784; i += 256) {
            int row = i >> 4, ch = i & 15;
            const float* src;
            if (row < 24)       src = g_ck + (size_t)row * (L_ * D_) + (size_t)l * 512 + head * 64 + ch * 4;
            else if (row < 48)  src = g_cv + (size_t)(row - 24) * (L_ * D_) + (size_t)l * 512 + head * 64 + ch * 4;
            else                src = g_q + (size_t)l * 512 + head * 64 + ch * 4;
            cp_async16((uint32_t)__cvta_generic_to_shared(&st[buf][row][ch * 4]), src);
        }
        CP_COMMIT();
    };

    stage(l0, 0);

    for (int li = 0; li < CL; li++) {
        const int buf = li & 1;
        CP_WAIT0();
        __syncthreads();
        if (li + 1 < CL) stage(l0 + li + 1, buf ^ 1);

        float z[16] = {};
        #pragma unroll
        for (int kf = 0; kf < KF_; kf++) {
            float ktv = st[buf][kf][e];
            const float4* vp = (const float4*)&st[buf][24 + kf][dg * 16];
            float4 v0 = vp[0], v1 = vp[1], v2 = vp[2], v3 = vp[3];
            z[0] += v0.x * ktv;  z[1] += v0.y * ktv;  z[2] += v0.z * ktv;  z[3] += v0.w * ktv;
            z[4] += v1.x * ktv;  z[5] += v1.y * ktv;  z[6] += v1.z * ktv;  z[7] += v1.w * ktv;
            z[8] += v2.x * ktv;  z[9] += v2.y * ktv;  z[10] += v2.z * ktv; z[11] += v2.w * ktv;
            z[12] += v3.x * ktv; z[13] += v3.y * ktv; z[14] += v3.z * ktv; z[15] += v3.w * ktv;
        }
        const float gate = gt[li];
        #pragma unroll
        for (int r = 0; r < 16; r++) S[r] += gate * scl[r] * z[r];

        // contraction with q over this thread's 16 d's
        const float4* qp = (const float4*)&st[buf][48][dg * 16];
        float4 q0 = qp[0], q1 = qp[1], q2 = qp[2], q3 = qp[3];
        float part =
            q0.x * S[0]  + q0.y * S[1]  + q0.z * S[2]  + q0.w * S[3] +
            q1.x * S[4]  + q1.y * S[5]  + q1.z * S[6]  + q1.w * S[7] +
            q2.x * S[8]  + q2.y * S[9]  + q2.z * S[10] + q2.w * S[11] +
            q3.x * S[12] + q3.y * S[13] + q3.z * S[14] + q3.w * S[15];
        red4[dg][e] = part;
        __syncthreads();
        if (dg == 0) {
            float o = (red4[0][e] + red4[1][e] + red4[2][e] + red4[3][e]) * cf[li];
            g_ctxt[(size_t)(l0 + li) * 512 + head * 64 + e] = o;
        }
    }
}

// ---------------- launch ----------------
extern "C" void kernel_launch(void* const* d_in, const int* in_sizes, int n_in,
                              void* d_out, int out_size) {
    const float* x   = (const float*)d_in[0];
    const float* Wq  = (const float*)d_in[1];
    const float* bq  = (const float*)d_in[2];
    const float* Wk  = (const float*)d_in[3];
    const float* bk  = (const float*)d_in[4];
    const float* Wv  = (const float*)d_in[5];
    const float* bv  = (const float*)d_in[6];
    const float* Wo  = (const float*)d_in[7];
    const float* bo  = (const float*)d_in[8];
    const float* Wg  = (const float*)d_in[9];
    const float* bg  = (const float*)d_in[10];
    const float* kvs = (const float*)d_in[11];
    const float* qks = (const float*)d_in[12];
    const float* flt = (const float*)d_in[13];
    float* out = (float*)d_out;

    void *pctxt;
    cudaGetSymbolAddress(&pctxt, g_ctxt);

    dim3 gblk(16, 16);

    qkv_gemm_kernel<<<dim3(8, 16, 3), gblk>>>(x, Wq, Wk, Wv, bq, bk, bv);

    norm_sim_kernel<<<L_, 512>>>(qks);

    prep_split_kernel<<<dim3(32, 16, 2), dim3(32, 8)>>>();
    prep_filters_kernel<<<48, 1024>>>(flt);

    conv_mma_kernel<<<dim3(8, 8, 24), 256>>>();

    zsum_kernel<<<dim3(NCH, H_), 256>>>(Wg, bg, kvs);

    coef_kernel<<<H_, 1024>>>();

    chunk_prefix_kernel<<<dim3(16, H_), 256>>>();

    ctxt_scan_kernel<<<dim3(NCH, H_), 256>>>(kvs);

    sgemm_bias_kernel<<<dim3(8, 16), gblk>>>((const float*)pctxt, Wo, bo, out);
}

// round 10
// speedup vs baseline: 2.8763x; 1.2297x over previous
#include <cuda_runtime.h>
#include <cuda_fp16.h>
#include <math.h>
#include <stdint.h>

#define L_   1024
#define D_   512
#define H_   8
#define HD_  64
#define KF_  24
#define EPSF 1e-5f
#define NCH  32
#define CL   32

// ---------------- static scratch ----------------
__device__ float g_q[L_ * D_];
__device__ float g_k[L_ * D_];
__device__ float g_v[L_ * D_];
__device__ float g_ck[(size_t)KF_ * L_ * D_];   // conv(k_norm): [kf][l][c]
__device__ float g_cv[(size_t)KF_ * L_ * D_];   // conv(v_norm)
__device__ float g_sim[H_ * L_];
__device__ float g_gate[H_ * L_];
__device__ float g_coef[H_ * L_];
__device__ float g_ctxt[L_ * D_];
__device__ float g_T[H_][NCH][4096];            // per-chunk gated-Z sums
__device__ float g_P[H_][NCH][4096];            // exclusive chunk prefix

// fp16 inputs for tensor-core conv
__device__ __half g_uTh[1024 * 1024];            // u_hi, [c (k:0-511, v:512-1023)][t]
__device__ __half g_fpad[2 * KF_ * 2048];        // [hi/lo][kf][1023 + lag]

// ---------------- mma.sync fp16 ----------------
__device__ __forceinline__ void mma16816(float* c, const uint32_t* a, const uint32_t* b) {
    asm volatile(
        "mma.sync.aligned.m16n8k16.row.col.f32.f16.f16.f32 "
        "{%0,%1,%2,%3}, {%4,%5,%6,%7}, {%8,%9}, {%0,%1,%2,%3};"
        : "+f"(c[0]), "+f"(c[1]), "+f"(c[2]), "+f"(c[3])
        : "r"(a[0]), "r"(a[1]), "r"(a[2]), "r"(a[3]), "r"(b[0]), "r"(b[1]));
}

__device__ __forceinline__ void cp_async16(uint32_t saddr, const void* gptr) {
    asm volatile("cp.async.cg.shared.global [%0], [%1], 16;" :: "r"(saddr), "l"(gptr));
}
#define CP_COMMIT() asm volatile("cp.async.commit_group;" ::: "memory")
#define CP_WAIT0()  asm volatile("cp.async.wait_group 0;" ::: "memory")

// ---------------- fused QKV SGEMM ----------------
__global__ void qkv_gemm_kernel(const float* __restrict__ A,
                                const float* __restrict__ Wq, const float* __restrict__ Wk,
                                const float* __restrict__ Wv,
                                const float* __restrict__ bq, const float* __restrict__ bk,
                                const float* __restrict__ bv) {
    __shared__ float As[64][17];
    __shared__ float Bs[16][64];
    const int tx = threadIdx.x, ty = threadIdx.y;
    const int tid = ty * 16 + tx;
    const int m0 = blockIdx.y * 64, n0 = blockIdx.x * 64;

    const float* B; const float* bias; float* C;
    if (blockIdx.z == 0)      { B = Wq; bias = bq; C = g_q; }
    else if (blockIdx.z == 1) { B = Wk; bias = bk; C = g_k; }
    else                      { B = Wv; bias = bv; C = g_v; }

    float acc[4][4] = {};
    for (int k0 = 0; k0 < 512; k0 += 16) {
        #pragma unroll
        for (int it = 0; it < 4; it++) {
            int e = tid + 256 * it;
            As[e >> 4][e & 15] = A[(m0 + (e >> 4)) * 512 + k0 + (e & 15)];
            Bs[e >> 6][e & 63] = B[(k0 + (e >> 6)) * 512 + n0 + (e & 63)];
        }
        __syncthreads();
        #pragma unroll
        for (int kk = 0; kk < 16; kk++) {
            float a[4], b[4];
            #pragma unroll
            for (int i = 0; i < 4; i++) a[i] = As[ty * 4 + i][kk];
            #pragma unroll
            for (int j = 0; j < 4; j++) b[j] = Bs[kk][tx * 4 + j];
            #pragma unroll
            for (int i = 0; i < 4; i++)
                #pragma unroll
                for (int j = 0; j < 4; j++)
                    acc[i][j] += a[i] * b[j];
        }
        __syncthreads();
    }
    #pragma unroll
    for (int i = 0; i < 4; i++)
        #pragma unroll
        for (int j = 0; j < 4; j++)
            C[(m0 + ty * 4 + i) * 512 + n0 + tx * 4 + j] = acc[i][j] + bias[n0 + tx * 4 + j];
}

// ---------------- plain SGEMM for the output projection ----------------
__global__ void sgemm_bias_kernel(const float* __restrict__ A,
                                  const float* __restrict__ B,
                                  const float* __restrict__ bias,
                                  float* __restrict__ C) {
    __shared__ float As[64][17];
    __shared__ float Bs[16][64];
    const int tx = threadIdx.x, ty = threadIdx.y;
    const int tid = ty * 16 + tx;
    const int m0 = blockIdx.y * 64, n0 = blockIdx.x * 64;

    float acc[4][4] = {};
    for (int k0 = 0; k0 < 512; k0 += 16) {
        #pragma unroll
        for (int it = 0; it < 4; it++) {
            int e = tid + 256 * it;
            As[e >> 4][e & 15] = A[(m0 + (e >> 4)) * 512 + k0 + (e & 15)];
            Bs[e >> 6][e & 63] = B[(k0 + (e >> 6)) * 512 + n0 + (e & 63)];
        }
        __syncthreads();
        #pragma unroll
        for (int kk = 0; kk < 16; kk++) {
            float a[4], b[4];
            #pragma unroll
            for (int i = 0; i < 4; i++) a[i] = As[ty * 4 + i][kk];
            #pragma unroll
            for (int j = 0; j < 4; j++) b[j] = Bs[kk][tx * 4 + j];
            #pragma unroll
            for (int i = 0; i < 4; i++)
                #pragma unroll
                for (int j = 0; j < 4; j++)
                    acc[i][j] += a[i] * b[j];
        }
        __syncthreads();
    }
    #pragma unroll
    for (int i = 0; i < 4; i++)
        #pragma unroll
        for (int j = 0; j < 4; j++)
            C[(m0 + ty * 4 + i) * 512 + n0 + tx * 4 + j] = acc[i][j] + bias[n0 + tx * 4 + j];
}

// ---------------- sim + in-place L2 norm ----------------
__global__ void norm_sim_kernel(const float* __restrict__ qk_scale) {
    const int l = blockIdx.x;
    const int c = threadIdx.x;
    const int head = c >> 6, d = c & 63;
    float q = g_q[l * 512 + c];
    float k = g_k[l * 512 + c];
    float v = g_v[l * 512 + c];

    __shared__ float sd[512], sk[512], sv[512];
    sd[c] = q * k; sk[c] = k * k; sv[c] = v * v;
    __syncthreads();
    for (int off = 32; off >= 1; off >>= 1) {
        if (d < off) {
            sd[c] += sd[c + off];
            sk[c] += sk[c + off];
            sv[c] += sv[c + off];
        }
        __syncthreads();
    }
    float nk = fmaxf(sqrtf(sk[head * 64]), 1e-12f);
    float nv = fmaxf(sqrtf(sv[head * 64]), 1e-12f);
    g_k[l * 512 + c] = k / nk;
    g_v[l * 512 + c] = v / nv;
    if (d == 0) g_sim[head * L_ + l] = sd[head * 64] * qk_scale[head];
}

// ---------------- prep: transpose + fp16 convert of normalized k,v ----------------
__global__ void prep_split_kernel() {
    __shared__ float tile[32][33];
    const int t0 = blockIdx.x * 32, c0 = blockIdx.y * 32, z = blockIdx.z;
    const float* __restrict__ src = z ? g_v : g_k;
    const int tx = threadIdx.x, ty = threadIdx.y;
    #pragma unroll
    for (int kk = 0; kk < 4; kk++) {
        int i = ty + 8 * kk;
        tile[i][tx] = src[(t0 + i) * 512 + c0 + tx];
    }
    __syncthreads();
    const int rb = z * 512;
    #pragma unroll
    for (int kk = 0; kk < 4; kk++) {
        int i = ty + 8 * kk;
        float v = tile[tx][i];
        g_uTh[(size_t)(rb + c0 + i) * 1024 + t0 + tx] = __float2half_rn(v);
    }
}

// ---------------- prep: padded filters fp16 hi/lo ----------------
__global__ void prep_filters_kernel(const float* __restrict__ flt) {
    int idx = blockIdx.x * 1024 + threadIdx.x;  // over 24*2048
    if (idx >= KF_ * 2048) return;
    int kf = idx >> 11, d = idx & 2047;
    float v = 0.0f;
    if (d >= 1023 && d < 2047) v = flt[(d - 1023) * KF_ + kf];
    __half hi = __float2half_rn(v);
    __half lo = __float2half_rn(v - __half2float(hi));
    g_fpad[idx] = hi;
    g_fpad[KF_ * 2048 + idx] = lo;
}

// ---------------- HMMA conv (fp16 2-term: (f_hi + f_lo) * u_hi) ----------------
#define BS_STRIDE 40

__global__ void __launch_bounds__(256) conv_mma_kernel() {
    __shared__ __align__(16) __half Bs[2][128][BS_STRIDE];   // [buf][c][t']
    __shared__ uint32_t fwp[2][2][160];                      // [buf][hi/lo][x] = {f[x], f[x-1]}

    const int tid = threadIdx.x;
    const int wid = tid >> 5, lane = tid & 31;
    const int g = lane >> 2, tg = lane & 3;
    const int wm = (wid & 3) * 32;
    const int wn = (wid >> 2) * 64;

    const int c0 = blockIdx.x * 128;
    const int l0 = (7 - blockIdx.y) * 128;
    const int kf = blockIdx.z;

    const __half* __restrict__ fp_hi = g_fpad + (size_t)kf * 2048;
    const __half* __restrict__ fp_lo = g_fpad + (size_t)(KF_ + kf) * 2048;

    const int nIter = (l0 + 128) >> 5;

    auto prefetch = [&](int it, int buf) {
        const int t0 = it << 5;
        #pragma unroll
        for (int r = 0; r < 2; r++) {
            int cidx = tid + 256 * r;            // 512 chunks of 16B
            int c = cidx >> 2, qq = cidx & 3;
            const __half* gsrc = g_uTh + (size_t)(c0 + c) * 1024 + t0 + qq * 8;
            uint32_t saddr = (uint32_t)__cvta_generic_to_shared(&Bs[buf][c][qq * 8]);
            cp_async16(saddr, gsrc);
        }
        CP_COMMIT();
        if (tid < 160) {
            int dmin = 1023 + (l0 - t0) - 31;
            uint32_t h0 = (uint32_t)__half_as_ushort(fp_hi[dmin + tid]);
            uint32_t h1 = (uint32_t)__half_as_ushort(fp_hi[dmin + tid - 1]);
            fwp[buf][0][tid] = h0 | (h1 << 16);
            uint32_t lo0 = (uint32_t)__half_as_ushort(fp_lo[dmin + tid]);
            uint32_t lo1 = (uint32_t)__half_as_ushort(fp_lo[dmin + tid - 1]);
            fwp[buf][1][tid] = lo0 | (lo1 << 16);
        }
    };

    float acc[2][8][4] = {};

    prefetch(0, 0);
    CP_WAIT0();
    __syncthreads();

    for (int it = 0; it < nIter; it++) {
        const int buf = it & 1;
        if (it + 1 < nIter) prefetch(it + 1, buf ^ 1);

        #pragma unroll
        for (int ks = 0; ks < 2; ks++) {
            const int kb = ks * 16;
            uint32_t a0[2][2], a1[2][2], a2[2][2];
            #pragma unroll
            for (int s = 0; s < 2; s++)
                #pragma unroll
                for (int i = 0; i < 2; i++) {
                    int x = wm + i * 16 + g - (kb + tg * 2) + 31;
                    a0[s][i] = fwp[buf][s][x];
                    a1[s][i] = fwp[buf][s][x + 8];
                    a2[s][i] = fwp[buf][s][x - 8];
                }
            #pragma unroll
            for (int j = 0; j < 8; j++) {
                int cc = wn + j * 8 + g;
                uint32_t bh[2];
                bh[0] = *(const uint32_t*)&Bs[buf][cc][kb + tg * 2];
                bh[1] = *(const uint32_t*)&Bs[buf][cc][kb + tg * 2 + 8];
                #pragma unroll
                for (int i = 0; i < 2; i++) {
                    uint32_t ah[4] = {a0[0][i], a1[0][i], a2[0][i], a0[0][i]};
                    uint32_t al[4] = {a0[1][i], a1[1][i], a2[1][i], a0[1][i]};
                    mma16816(acc[i][j], ah, bh);   // f_hi * u_hi
                    mma16816(acc[i][j], al, bh);   // f_lo * u_hi
                }
            }
        }
        if (it + 1 < nIter) CP_WAIT0();
        __syncthreads();
    }

    float* __restrict__ base = (c0 < 512) ? g_ck : g_cv;
    const int cb0 = (c0 < 512) ? c0 : c0 - 512;
    #pragma unroll
    for (int i = 0; i < 2; i++) {
        int r = l0 + wm + i * 16 + g;
        #pragma unroll
        for (int j = 0; j < 8; j++) {
            int cc = cb0 + wn + j * 8 + tg * 2;
            size_t o0 = ((size_t)kf * 1024 + r) * 512 + cc;
            size_t o1 = ((size_t)kf * 1024 + r + 8) * 512 + cc;
            *(float2*)(base + o0) = make_float2(acc[i][j][0], acc[i][j][1]);
            *(float2*)(base + o1) = make_float2(acc[i][j][2], acc[i][j][3]);
        }
    }
}

// ---------------- Pass A: per-chunk gated-Z totals + gates ----------------
__global__ void __launch_bounds__(256) zsum_kernel(const float* __restrict__ Wg,
                                                   const float* __restrict__ bg,
                                                   const float* __restrict__ kvscale) {
    const int chunk = blockIdx.x, head = blockIdx.y;
    const int tid = threadIdx.x;
    const int e = tid & 63, dg = tid >> 6;
    const int l0 = chunk * CL;

    __shared__ __align__(16) float st[2][48][64];   // rows 0..23 ck, 24..47 cv
    __shared__ float red[8];
    __shared__ float gsh;

    float scl[16], wg[16];
    #pragma unroll
    for (int r = 0; r < 16; r++) {
        int m = (dg * 16 + r) * 64 + e;
        scl[r] = kvscale[head * 4096 + m];
        wg[r] = Wg[m];
    }
    const float bgv = bg[0];

    auto stage = [&](int l, int buf) {
        for (int i = tid; i < 768; i += 256) {
            int row = i >> 4, ch = i & 15;
            const float* src = ((row < 24) ? (g_ck + (size_t)row * (L_ * D_))
                                           : (g_cv + (size_t)(row - 24) * (L_ * D_)))
                               + (size_t)l * 512 + head * 64 + ch * 4;
            cp_async16((uint32_t)__cvta_generic_to_shared(&st[buf][row][ch * 4]), src);
        }
        CP_COMMIT();
    };

    float S[16] = {};
    stage(l0, 0);

    for (int li = 0; li < CL; li++) {
        const int buf = li & 1;
        CP_WAIT0();
        __syncthreads();
        if (li + 1 < CL) stage(l0 + li + 1, buf ^ 1);

        float z[16] = {};
        #pragma unroll
        for (int kf = 0; kf < KF_; kf++) {
            float ktv = st[buf][kf][e];
            const float4* vp = (const float4*)&st[buf][24 + kf][dg * 16];
            float4 v0 = vp[0], v1 = vp[1], v2 = vp[2], v3 = vp[3];
            z[0] += v0.x * ktv;  z[1] += v0.y * ktv;  z[2] += v0.z * ktv;  z[3] += v0.w * ktv;
            z[4] += v1.x * ktv;  z[5] += v1.y * ktv;  z[6] += v1.z * ktv;  z[7] += v1.w * ktv;
            z[8] += v2.x * ktv;  z[9] += v2.y * ktv;  z[10] += v2.z * ktv; z[11] += v2.w * ktv;
            z[12] += v3.x * ktv; z[13] += v3.y * ktv; z[14] += v3.z * ktv; z[15] += v3.w * ktv;
        }
        float lp = 0.0f;
        #pragma unroll
        for (int r = 0; r < 16; r++) {
            z[r] *= scl[r];
            lp += z[r] * wg[r];
        }
        #pragma unroll
        for (int off = 16; off >= 1; off >>= 1)
            lp += __shfl_xor_sync(0xffffffffu, lp, off);
        if ((tid & 31) == 0) red[tid >> 5] = lp;
        __syncthreads();
        if (tid == 0) {
            float s = red[0] + red[1] + red[2] + red[3] + red[4] + red[5] + red[6] + red[7];
            float logit = s + bgv;
            float rl = fmaxf(logit, 0.0f);
            float gate = rl * rl + EPSF;
            gsh = gate;
            g_gate[head * L_ + l0 + li] = gate;
        }
        __syncthreads();
        float gate = gsh;
        #pragma unroll
        for (int r = 0; r < 16; r++) S[r] += gate * z[r];
    }

    #pragma unroll
    for (int r = 0; r < 16; r++)
        g_T[head][chunk][(dg * 16 + r) * 64 + e] = S[r];
}

// ---------------- Pass B: exclusive chunk prefix ----------------
__global__ void chunk_prefix_kernel() {
    const int head = blockIdx.y;
    const int comp = blockIdx.x * 256 + threadIdx.x;   // 0..4095
    float run = 0.0f;
    #pragma unroll
    for (int ch = 0; ch < NCH; ch++) {
        float t = g_T[head][ch][comp];
        g_P[head][ch][comp] = run;
        run += t;
    }
}

// ---------------- parallel scan: online softmax (m,s) + gate cumsum -> coef ----------------
__global__ void coef_kernel() {
    const int head = blockIdx.x;
    const int i = threadIdx.x;   // 1024
    __shared__ float sm[1024], ss[1024], sg[1024];
    float si = g_sim[head * L_ + i];
    sm[i] = si; ss[i] = 1.0f; sg[i] = g_gate[head * L_ + i];
    __syncthreads();
    for (int off = 1; off < 1024; off <<= 1) {
        float mp = 0.f, sp = 0.f, gp = 0.f;
        bool has = (i >= off);
        if (has) { mp = sm[i - off]; sp = ss[i - off]; gp = sg[i - off]; }
        __syncthreads();
        if (has) {
            float mi = sm[i], s_i = ss[i];
            float mn = fmaxf(mp, mi);
            ss[i] = sp * __expf(mp - mn) + s_i * __expf(mi - mn);
            sm[i] = mn;
            sg[i] += gp;
        }
        __syncthreads();
    }
    float w = __expf(si - sm[i]) / (ss[i] + EPSF);
    float silu = w / (1.0f + __expf(-w));
    g_coef[head * L_ + i] = (1.0f + silu) / (sg[i] + EPSF);
}

// ---------------- Pass C: running scan + q contraction -> ctxt ----------------
__global__ void __launch_bounds__(256) ctxt_scan_kernel(const float* __restrict__ kvscale) {
    const int chunk = blockIdx.x, head = blockIdx.y;
    const int tid = threadIdx.x;
    const int e = tid & 63, dg = tid >> 6;
    const int l0 = chunk * CL;

    __shared__ __align__(16) float st[2][49][64];   // rows 0..23 ck, 24..47 cv, 48 q
    __shared__ float red4[4][64];
    __shared__ float gt[CL], cf[CL];

    float scl[16];
    #pragma unroll
    for (int r = 0; r < 16; r++)
        scl[r] = kvscale[head * 4096 + (dg * 16 + r) * 64 + e];

    if (tid < CL) {
        gt[tid] = g_gate[head * L_ + l0 + tid];
        cf[tid] = g_coef[head * L_ + l0 + tid];
    }

    float S[16];
    #pragma unroll
    for (int r = 0; r < 16; r++)
        S[r] = g_P[head][chunk][(dg * 16 + r) * 64 + e];

    auto stage = [&](int l, int buf) {
        for (int i = tid; i < 784; i += 256) {
            int row = i >> 4, ch = i & 15;
            const float* src;
            if (row < 24)       src = g_ck + (size_t)row * (L_ * D_) + (size_t)l * 512 + head * 64 + ch * 4;
            else if (row < 48)  src = g_cv + (size_t)(row - 24) * (L_ * D_) + (size_t)l * 512 + head * 64 + ch * 4;
            else                src = g_q + (size_t)l * 512 + head * 64 + ch * 4;
            cp_async16((uint32_t)__cvta_generic_to_shared(&st[buf][row][ch * 4]), src);
        }
        CP_COMMIT();
    };

    stage(l0, 0);

    for (int li = 0; li < CL; li++) {
        const int buf = li & 1;
        CP_WAIT0();
        __syncthreads();
        if (li + 1 < CL) stage(l0 + li + 1, buf ^ 1);

        float z[16] = {};
        #pragma unroll
        for (int kf = 0; kf < KF_; kf++) {
            float ktv = st[buf][kf][e];
            const float4* vp = (const float4*)&st[buf][24 + kf][dg * 16];
            float4 v0 = vp[0], v1 = vp[1], v2 = vp[2], v3 = vp[3];
            z[0] += v0.x * ktv;  z[1] += v0.y * ktv;  z[2] += v0.z * ktv;  z[3] += v0.w * ktv;
            z[4] += v1.x * ktv;  z[5] += v1.y * ktv;  z[6] += v1.z * ktv;  z[7] += v1.w * ktv;
            z[8] += v2.x * ktv;  z[9] += v2.y * ktv;  z[10] += v2.z * ktv; z[11] += v2.w * ktv;
            z[12] += v3.x * ktv; z[13] += v3.y * ktv; z[14] += v3.z * ktv; z[15] += v3.w * ktv;
        }
        const float gate = gt[li];
        #pragma unroll
        for (int r = 0; r < 16; r++) S[r] += gate * scl[r] * z[r];

        const float4* qp = (const float4*)&st[buf][48][dg * 16];
        float4 q0 = qp[0], q1 = qp[1], q2 = qp[2], q3 = qp[3];
        float part =
            q0.x * S[0]  + q0.y * S[1]  + q0.z * S[2]  + q0.w * S[3] +
            q1.x * S[4]  + q1.y * S[5]  + q1.z * S[6]  + q1.w * S[7] +
            q2.x * S[8]  + q2.y * S[9]  + q2.z * S[10] + q2.w * S[11] +
            q3.x * S[12] + q3.y * S[13] + q3.z * S[14] + q3.w * S[15];
        red4[dg][e] = part;
        __syncthreads();
        if (dg == 0) {
            float o = (red4[0][e] + red4[1][e] + red4[2][e] + red4[3][e]) * cf[li];
            g_ctxt[(size_t)(l0 + li) * 512 + head * 64 + e] = o;
        }
    }
}

// ---------------- launch ----------------
extern "C" void kernel_launch(void* const* d_in, const int* in_sizes, int n_in,
                              void* d_out, int out_size) {
    const float* x   = (const float*)d_in[0];
    const float* Wq  = (const float*)d_in[1];
    const float* bq  = (const float*)d_in[2];
    const float* Wk  = (const float*)d_in[3];
    const float* bk  = (const float*)d_in[4];
    const float* Wv  = (const float*)d_in[5];
    const float* bv  = (const float*)d_in[6];
    const float* Wo  = (const float*)d_in[7];
    const float* bo  = (const float*)d_in[8];
    const float* Wg  = (const float*)d_in[9];
    const float* bg  = (const float*)d_in[10];
    const float* kvs = (const float*)d_in[11];
    const float* qks = (const float*)d_in[12];
    const float* flt = (const float*)d_in[13];
    float* out = (float*)d_out;

    void *pctxt;
    cudaGetSymbolAddress(&pctxt, g_ctxt);

    dim3 gblk(16, 16);

    qkv_gemm_kernel<<<dim3(8, 16, 3), gblk>>>(x, Wq, Wk, Wv, bq, bk, bv);

    norm_sim_kernel<<<L_, 512>>>(qks);

    prep_split_kernel<<<dim3(32, 16, 2), dim3(32, 8)>>>();
    prep_filters_kernel<<<48, 1024>>>(flt);

    conv_mma_kernel<<<dim3(8, 8, 24), 256>>>();

    zsum_kernel<<<dim3(NCH, H_), 256>>>(Wg, bg, kvs);

    coef_kernel<<<H_, 1024>>>();

    chunk_prefix_kernel<<<dim3(16, H_), 256>>>();

    ctxt_scan_kernel<<<dim3(NCH, H_), 256>>>(kvs);

    sgemm_bias_kernel<<<dim3(8, 16), gblk>>>((const float*)pctxt, Wo, bo, out);
}